// round 1
// baseline (speedup 1.0000x reference)
#include <cuda_runtime.h>
#include <math.h>

// ---------------------------------------------------------------------------
// ResidualAttentionBlock: x[1024,8,1024] fp32, D=1024, H=16, c=64
// Pipeline:
//   ln1 (remap s-major -> n-major) -> gemm qkv -> flash attention ->
//   gemm out-proj (+bias, +residual x, remap n-major -> s-major) ->
//   ln2 -> gemm fc (+bias, QuickGELU) -> gemm proj (+bias, +residual) -> d_out
// ---------------------------------------------------------------------------

#define NTOK 8192
#define DMODEL 1024

// Scratch (device globals: the allowed alloc-free path)
__device__ float g_h[NTOK * DMODEL];        // LN1 out, n-major
__device__ float g_qkv[NTOK * 3 * DMODEL];  // n-major
__device__ float g_attn[NTOK * DMODEL];     // n-major
__device__ float g_x1[NTOK * DMODEL];       // x + attn_out, s-major
__device__ float g_h2[NTOK * DMODEL];       // LN2 out, s-major
__device__ float g_fc[NTOK * 4 * DMODEL];   // s-major

// ---------------------------------------------------------------------------
// LayerNorm: one block per row (256 threads, 4 elems/thread).
// remap=1: input row r (s-major, r = s*8+n) writes output row n*1024+s.
// ---------------------------------------------------------------------------
__global__ void __launch_bounds__(256) ln_kernel(
    const float* __restrict__ in, const float* __restrict__ w,
    const float* __restrict__ b, float* __restrict__ out, int remap) {
  int row = blockIdx.x;
  int out_row = remap ? ((row & 7) * 1024 + (row >> 3)) : row;
  const float* xr = in + (size_t)row * DMODEL;
  int t = threadIdx.x;
  float v[4];
  float s = 0.f, ss = 0.f;
#pragma unroll
  for (int i = 0; i < 4; i++) {
    v[i] = xr[t + 256 * i];
    s += v[i];
    ss += v[i] * v[i];
  }
#pragma unroll
  for (int o = 16; o > 0; o >>= 1) {
    s += __shfl_xor_sync(0xffffffffu, s, o);
    ss += __shfl_xor_sync(0xffffffffu, ss, o);
  }
  __shared__ float rs[8], rss[8];
  int warp = t >> 5, lane = t & 31;
  if (lane == 0) { rs[warp] = s; rss[warp] = ss; }
  __syncthreads();
  if (t == 0) {
    float a = 0.f, c = 0.f;
#pragma unroll
    for (int i = 0; i < 8; i++) { a += rs[i]; c += rss[i]; }
    rs[0] = a; rss[0] = c;
  }
  __syncthreads();
  float mean = rs[0] * (1.f / 1024.f);
  float var = rss[0] * (1.f / 1024.f) - mean * mean;
  float rstd = rsqrtf(var + 1e-5f);
  float* orow = out + (size_t)out_row * DMODEL;
#pragma unroll
  for (int i = 0; i < 4; i++) {
    int c = t + 256 * i;
    orow[c] = (v[i] - mean) * rstd * w[c] + b[c];
  }
}

// ---------------------------------------------------------------------------
// NT SGEMM: C[m][n] = sum_k A[m][k] * B[n][k] + bias[n]  (both row-major)
// 128x128 block tile, BK=8, 256 threads, 8x8 per thread.
// EPI: 0 = bias only, 1 = bias + QuickGELU, 2 = bias + residual add
// REMAP: store row m = n_*1024+s at row s*8+n_ (and read residual there).
// M = gridDim.y*128 (implicit). All dims multiples of tile sizes.
// ---------------------------------------------------------------------------
template <int EPI, bool REMAP>
__global__ void __launch_bounds__(256) gemm_nt(
    const float* __restrict__ A, const float* __restrict__ B,
    const float* __restrict__ bias, const float* __restrict__ res,
    float* __restrict__ C, int N, int K) {
  __shared__ float As[8][128];
  __shared__ float Bs[8][128];
  int tid = threadIdx.x;
  const float* Ab = A + (size_t)blockIdx.y * 128 * K;
  const float* Bb = B + (size_t)blockIdx.x * 128 * K;
  int lrow = tid >> 1;          // 0..127
  int lcol = (tid & 1) * 4;     // 0 or 4
  int tm = (tid >> 4) * 8;      // 0..120
  int tn = (tid & 15) * 8;      // 0..120

  float acc[8][8];
#pragma unroll
  for (int i = 0; i < 8; i++)
#pragma unroll
    for (int j = 0; j < 8; j++) acc[i][j] = 0.f;

  for (int k0 = 0; k0 < K; k0 += 8) {
    float4 a4 = *(const float4*)(Ab + (size_t)lrow * K + k0 + lcol);
    float4 b4 = *(const float4*)(Bb + (size_t)lrow * K + k0 + lcol);
    As[lcol + 0][lrow] = a4.x; As[lcol + 1][lrow] = a4.y;
    As[lcol + 2][lrow] = a4.z; As[lcol + 3][lrow] = a4.w;
    Bs[lcol + 0][lrow] = b4.x; Bs[lcol + 1][lrow] = b4.y;
    Bs[lcol + 2][lrow] = b4.z; Bs[lcol + 3][lrow] = b4.w;
    __syncthreads();
#pragma unroll
    for (int k = 0; k < 8; k++) {
      float4 a0 = *(const float4*)&As[k][tm];
      float4 a1 = *(const float4*)&As[k][tm + 4];
      float4 b0 = *(const float4*)&Bs[k][tn];
      float4 b1 = *(const float4*)&Bs[k][tn + 4];
      float ar[8] = {a0.x, a0.y, a0.z, a0.w, a1.x, a1.y, a1.z, a1.w};
      float br[8] = {b0.x, b0.y, b0.z, b0.w, b1.x, b1.y, b1.z, b1.w};
#pragma unroll
      for (int i = 0; i < 8; i++)
#pragma unroll
        for (int j = 0; j < 8; j++) acc[i][j] += ar[i] * br[j];
    }
    __syncthreads();
  }

  int m0 = blockIdx.y * 128 + tm;
  int n0 = blockIdx.x * 128 + tn;
#pragma unroll
  for (int i = 0; i < 8; i++) {
    int m = m0 + i;
    int om = REMAP ? ((m & 1023) * 8 + (m >> 10)) : m;
    float* crow = C + (size_t)om * N;
    const float* rrow = res + (size_t)om * N;  // only dereferenced if EPI==2
#pragma unroll
    for (int j = 0; j < 8; j++) {
      float v = acc[i][j] + bias[n0 + j];
      if (EPI == 1) v = v * (1.f / (1.f + __expf(-1.702f * v)));  // QuickGELU
      if (EPI == 2) v += rrow[n0 + j];
      crow[n0 + j] = v;
    }
  }
}

// ---------------------------------------------------------------------------
// Flash attention: grid (16 q-tiles, 16 heads, 8 batches), 256 threads.
// qkv rows are n-major: row = n*1024 + s, cols: q at h*64, k at 1024+h*64,
// v at 2048+h*64. Each block: 64 queries x full 1024 keys, online softmax.
// Thread t owns query row i = t/4 and column group g = t&3 (16 cols / thread).
// Shared: QsT [c][i], KVs (K as [c][j], then V as [j][c]), PsT [j][i] = 48 KB.
// ---------------------------------------------------------------------------
__global__ void __launch_bounds__(256) attn_kernel(
    const float* __restrict__ qkv, float* __restrict__ out) {
  __shared__ float QsT[64][64];
  __shared__ float KVs[64][64];
  __shared__ float PsT[64][64];
  int n = blockIdx.z, hh = blockIdx.y;
  int q0 = blockIdx.x * 64;
  int t = threadIdx.x;
  const float* base = qkv + (size_t)n * 1024 * 3072;

  for (int e = t; e < 4096; e += 256) {
    int i = e >> 6, c = e & 63;
    QsT[c][i] = base[(size_t)(q0 + i) * 3072 + hh * 64 + c] * 0.125f;  // /sqrt(64)
  }

  int i = t >> 2;
  int g = t & 3;
  int c0 = g * 16;
  float m = -1e30f, l = 0.f;
  float o[16];
#pragma unroll
  for (int cc = 0; cc < 16; cc++) o[cc] = 0.f;
  __syncthreads();

  for (int k0 = 0; k0 < 1024; k0 += 64) {
    // K tile, transposed [c][j]
    for (int e = t; e < 4096; e += 256) {
      int j = e >> 6, c = e & 63;
      KVs[c][j] = base[(size_t)(k0 + j) * 3072 + 1024 + hh * 64 + c];
    }
    __syncthreads();

    float s[16];
#pragma unroll
    for (int jj = 0; jj < 16; jj++) s[jj] = 0.f;
#pragma unroll 4
    for (int c = 0; c < 64; c++) {
      float qv = QsT[c][i];
#pragma unroll
      for (int jj = 0; jj < 16; jj++) s[jj] += qv * KVs[c][g + jj * 4];
    }

    // online softmax (4 threads per row, aligned shfl groups)
    float mt = s[0];
#pragma unroll
    for (int jj = 1; jj < 16; jj++) mt = fmaxf(mt, s[jj]);
    mt = fmaxf(mt, __shfl_xor_sync(0xffffffffu, mt, 1));
    mt = fmaxf(mt, __shfl_xor_sync(0xffffffffu, mt, 2));
    float mn = fmaxf(m, mt);
    float alpha = __expf(m - mn);
    float lt = 0.f;
#pragma unroll
    for (int jj = 0; jj < 16; jj++) {
      s[jj] = __expf(s[jj] - mn);
      lt += s[jj];
    }
    lt += __shfl_xor_sync(0xffffffffu, lt, 1);
    lt += __shfl_xor_sync(0xffffffffu, lt, 2);
    l = l * alpha + lt;
    m = mn;
#pragma unroll
    for (int cc = 0; cc < 16; cc++) o[cc] *= alpha;
#pragma unroll
    for (int jj = 0; jj < 16; jj++) PsT[g + jj * 4][i] = s[jj];
    __syncthreads();  // P written; everyone done reading K

    // V tile, [j][c]
    for (int e = t; e < 4096; e += 256) {
      int j = e >> 6, c = e & 63;
      KVs[j][c] = base[(size_t)(k0 + j) * 3072 + 2048 + hh * 64 + c];
    }
    __syncthreads();

#pragma unroll 4
    for (int j = 0; j < 64; j++) {
      float pv = PsT[j][i];
      float4 v0 = *(const float4*)&KVs[j][c0];
      float4 v1 = *(const float4*)&KVs[j][c0 + 4];
      float4 v2 = *(const float4*)&KVs[j][c0 + 8];
      float4 v3 = *(const float4*)&KVs[j][c0 + 12];
      o[0] += pv * v0.x;  o[1] += pv * v0.y;  o[2] += pv * v0.z;  o[3] += pv * v0.w;
      o[4] += pv * v1.x;  o[5] += pv * v1.y;  o[6] += pv * v1.z;  o[7] += pv * v1.w;
      o[8] += pv * v2.x;  o[9] += pv * v2.y;  o[10] += pv * v2.z; o[11] += pv * v2.w;
      o[12] += pv * v3.x; o[13] += pv * v3.y; o[14] += pv * v3.z; o[15] += pv * v3.w;
    }
    __syncthreads();  // done with P and V before next tile overwrites
  }

  float rl = 1.f / l;
  float* orow = out + (size_t)(n * 1024 + q0 + i) * 1024 + hh * 64;
#pragma unroll
  for (int cc = 0; cc < 16; cc++) orow[c0 + cc] = o[cc] * rl;
}

// ---------------------------------------------------------------------------
extern "C" void kernel_launch(void* const* d_in, const int* in_sizes, int n_in,
                              void* d_out, int out_size) {
  const float* x      = (const float*)d_in[0];
  const float* ln1_w  = (const float*)d_in[1];
  const float* ln1_b  = (const float*)d_in[2];
  const float* in_w   = (const float*)d_in[3];
  const float* in_b   = (const float*)d_in[4];
  const float* out_w  = (const float*)d_in[5];
  const float* out_b  = (const float*)d_in[6];
  const float* ln2_w  = (const float*)d_in[7];
  const float* ln2_b  = (const float*)d_in[8];
  const float* fc_w   = (const float*)d_in[9];
  const float* fc_b   = (const float*)d_in[10];
  const float* proj_w = (const float*)d_in[11];
  const float* proj_b = (const float*)d_in[12];
  float* out = (float*)d_out;

  float *h, *qkv, *attn, *x1, *h2, *fc;
  cudaGetSymbolAddress((void**)&h, g_h);
  cudaGetSymbolAddress((void**)&qkv, g_qkv);
  cudaGetSymbolAddress((void**)&attn, g_attn);
  cudaGetSymbolAddress((void**)&x1, g_x1);
  cudaGetSymbolAddress((void**)&h2, g_h2);
  cudaGetSymbolAddress((void**)&fc, g_fc);

  // 1. LN1, write n-major
  ln_kernel<<<8192, 256>>>(x, ln1_w, ln1_b, h, 1);
  // 2. qkv = h @ in_w^T + in_b          [8192 x 3072]
  gemm_nt<0, false><<<dim3(24, 64), 256>>>(h, in_w, in_b, nullptr, qkv, 3072, 1024);
  // 3. attention -> attn (n-major)      [8192 x 1024]
  attn_kernel<<<dim3(16, 16, 8), 256>>>(qkv, attn);
  // 4. x1 = x + attn @ out_w^T + out_b  (remap to s-major)
  gemm_nt<2, true><<<dim3(8, 64), 256>>>(attn, out_w, out_b, x, x1, 1024, 1024);
  // 5. LN2
  ln_kernel<<<8192, 256>>>(x1, ln2_w, ln2_b, h2, 0);
  // 6. fc = QuickGELU(h2 @ fc_w^T + fc_b)  [8192 x 4096]
  gemm_nt<1, false><<<dim3(32, 64), 256>>>(h2, fc_w, fc_b, nullptr, fc, 4096, 1024);
  // 7. out = x1 + fc @ proj_w^T + proj_b   [8192 x 1024]
  gemm_nt<2, false><<<dim3(8, 64), 256>>>(fc, proj_w, proj_b, x1, out, 1024, 4096);
}

// round 2
// speedup vs baseline: 1.6452x; 1.6452x over previous
#include <cuda_runtime.h>
#include <math.h>
#include <stdint.h>

// ---------------------------------------------------------------------------
// ResidualAttentionBlock: x[1024,8,1024] fp32, D=1024, H=16, c=64
//   ln1 (remap s-major -> n-major) -> tf32 gemm qkv -> flash attention ->
//   tf32 gemm out-proj (+bias,+residual, remap) -> ln2 ->
//   tf32 gemm fc (+bias, QuickGELU) -> tf32 gemm proj (+bias,+residual) -> out
// ---------------------------------------------------------------------------

#define NTOK 8192
#define DMODEL 1024

__device__ float g_h[NTOK * DMODEL];
__device__ float g_qkv[NTOK * 3 * DMODEL];
__device__ float g_attn[NTOK * DMODEL];
__device__ float g_x1[NTOK * DMODEL];
__device__ float g_h2[NTOK * DMODEL];
__device__ float g_fc[NTOK * 4 * DMODEL];

// ---------------------------------------------------------------------------
// LayerNorm (unchanged from R1)
// ---------------------------------------------------------------------------
__global__ void __launch_bounds__(256) ln_kernel(
    const float* __restrict__ in, const float* __restrict__ w,
    const float* __restrict__ b, float* __restrict__ out, int remap) {
  int row = blockIdx.x;
  int out_row = remap ? ((row & 7) * 1024 + (row >> 3)) : row;
  const float* xr = in + (size_t)row * DMODEL;
  int t = threadIdx.x;
  float v[4];
  float s = 0.f, ss = 0.f;
#pragma unroll
  for (int i = 0; i < 4; i++) {
    v[i] = xr[t + 256 * i];
    s += v[i];
    ss += v[i] * v[i];
  }
#pragma unroll
  for (int o = 16; o > 0; o >>= 1) {
    s += __shfl_xor_sync(0xffffffffu, s, o);
    ss += __shfl_xor_sync(0xffffffffu, ss, o);
  }
  __shared__ float rs[8], rss[8];
  int warp = t >> 5, lane = t & 31;
  if (lane == 0) { rs[warp] = s; rss[warp] = ss; }
  __syncthreads();
  if (t == 0) {
    float a = 0.f, c = 0.f;
#pragma unroll
    for (int i = 0; i < 8; i++) { a += rs[i]; c += rss[i]; }
    rs[0] = a; rss[0] = c;
  }
  __syncthreads();
  float mean = rs[0] * (1.f / 1024.f);
  float var = rss[0] * (1.f / 1024.f) - mean * mean;
  float rstd = rsqrtf(var + 1e-5f);
  float* orow = out + (size_t)out_row * DMODEL;
#pragma unroll
  for (int i = 0; i < 4; i++) {
    int c = t + 256 * i;
    orow[c] = (v[i] - mean) * rstd * w[c] + b[c];
  }
}

// ---------------------------------------------------------------------------
// tf32 tensor-core NT GEMM: C[m][n] = sum_k A[m][k]*B[n][k] + bias[n]
// 128x128 block tile, BK=16, 2-stage cp.async pipeline, 8 warps.
// Warp grid 2(m) x 4(n): 64x32 warp tile = 4x4 m16n8k8 mma tiles.
// Shared rows padded to 20 floats -> conflict-free fragment loads.
// EPI: 0 bias, 1 bias+QuickGELU, 2 bias+residual.  REMAP: n-major->s-major.
// ---------------------------------------------------------------------------
__device__ __forceinline__ uint32_t f2tf32(float v) {
  uint32_t r;
  asm("cvt.rna.tf32.f32 %0, %1;" : "=r"(r) : "f"(v));
  return r;
}

template <int EPI, bool REMAP>
__global__ void __launch_bounds__(256) gemm_tc(
    const float* __restrict__ A, const float* __restrict__ B,
    const float* __restrict__ bias, const float* __restrict__ res,
    float* __restrict__ C, int N, int K) {
  __shared__ __align__(16) float As[2][128][20];
  __shared__ __align__(16) float Bs[2][128][20];
  int tid = threadIdx.x;
  int lane = tid & 31, warp = tid >> 5;
  int wm = warp >> 2, wn = warp & 3;
  const float* Ab = A + (size_t)blockIdx.y * 128 * K;
  const float* Bb = B + (size_t)blockIdx.x * 128 * K;

  float acc[4][4][4];
#pragma unroll
  for (int mi = 0; mi < 4; mi++)
#pragma unroll
    for (int ni = 0; ni < 4; ni++)
#pragma unroll
      for (int r = 0; r < 4; r++) acc[mi][ni][r] = 0.f;

  // stage loader: 128 rows x 16 cols of A and B -> shared buf
  auto load_stage = [&](int kt, int buf) {
#pragma unroll
    for (int it = 0; it < 2; it++) {
      int task = tid + it * 256;
      int row = task >> 2, c4 = (task & 3) << 2;
      const float* sa = Ab + (size_t)row * K + kt * 16 + c4;
      const float* sb = Bb + (size_t)row * K + kt * 16 + c4;
      uint32_t da = (uint32_t)__cvta_generic_to_shared(&As[buf][row][c4]);
      uint32_t db = (uint32_t)__cvta_generic_to_shared(&Bs[buf][row][c4]);
      asm volatile("cp.async.cg.shared.global [%0], [%1], 16;" ::"r"(da), "l"(sa));
      asm volatile("cp.async.cg.shared.global [%0], [%1], 16;" ::"r"(db), "l"(sb));
    }
    asm volatile("cp.async.commit_group;");
  };

  int KT = K >> 4;
  load_stage(0, 0);

  for (int kt = 0; kt < KT; kt++) {
    int buf = kt & 1;
    if (kt + 1 < KT) {
      load_stage(kt + 1, buf ^ 1);
      asm volatile("cp.async.wait_group 1;");
    } else {
      asm volatile("cp.async.wait_group 0;");
    }
    __syncthreads();

#pragma unroll
    for (int ks = 0; ks < 2; ks++) {
      uint32_t af[4][4], bf[4][2];
      int ar = lane >> 2;
      int ac = ks * 8 + (lane & 3);
#pragma unroll
      for (int mi = 0; mi < 4; mi++) {
        int r = wm * 64 + mi * 16 + ar;
        af[mi][0] = f2tf32(As[buf][r][ac]);
        af[mi][1] = f2tf32(As[buf][r + 8][ac]);
        af[mi][2] = f2tf32(As[buf][r][ac + 4]);
        af[mi][3] = f2tf32(As[buf][r + 8][ac + 4]);
      }
#pragma unroll
      for (int ni = 0; ni < 4; ni++) {
        int n = wn * 32 + ni * 8 + ar;
        bf[ni][0] = f2tf32(Bs[buf][n][ac]);
        bf[ni][1] = f2tf32(Bs[buf][n][ac + 4]);
      }
#pragma unroll
      for (int mi = 0; mi < 4; mi++)
#pragma unroll
        for (int ni = 0; ni < 4; ni++) {
          asm volatile(
              "mma.sync.aligned.m16n8k8.row.col.f32.tf32.tf32.f32 "
              "{%0,%1,%2,%3}, {%4,%5,%6,%7}, {%8,%9}, {%0,%1,%2,%3};"
              : "+f"(acc[mi][ni][0]), "+f"(acc[mi][ni][1]),
                "+f"(acc[mi][ni][2]), "+f"(acc[mi][ni][3])
              : "r"(af[mi][0]), "r"(af[mi][1]), "r"(af[mi][2]), "r"(af[mi][3]),
                "r"(bf[ni][0]), "r"(bf[ni][1]));
        }
    }
    __syncthreads();
  }

  // epilogue
#pragma unroll
  for (int mi = 0; mi < 4; mi++) {
#pragma unroll
    for (int half = 0; half < 2; half++) {
      int r = blockIdx.y * 128 + wm * 64 + mi * 16 + (lane >> 2) + half * 8;
      int om = REMAP ? ((r & 1023) * 8 + (r >> 10)) : r;
      float* crow = C + (size_t)om * N;
      const float* rrow = (EPI == 2) ? res + (size_t)om * N : nullptr;
#pragma unroll
      for (int ni = 0; ni < 4; ni++) {
        int cix = blockIdx.x * 128 + wn * 32 + ni * 8 + (lane & 3) * 2;
        float v0 = acc[mi][ni][half * 2 + 0] + bias[cix];
        float v1 = acc[mi][ni][half * 2 + 1] + bias[cix + 1];
        if (EPI == 1) {
          v0 = v0 * (1.f / (1.f + __expf(-1.702f * v0)));
          v1 = v1 * (1.f / (1.f + __expf(-1.702f * v1)));
        }
        if (EPI == 2) {
          v0 += rrow[cix];
          v1 += rrow[cix + 1];
        }
        *(float2*)&crow[cix] = make_float2(v0, v1);
      }
    }
  }
}

// ---------------------------------------------------------------------------
// Flash attention (unchanged from R1): grid (16 q-tiles, 16 heads, 8 batches)
// ---------------------------------------------------------------------------
__global__ void __launch_bounds__(256) attn_kernel(
    const float* __restrict__ qkv, float* __restrict__ out) {
  __shared__ float QsT[64][64];
  __shared__ float KVs[64][64];
  __shared__ float PsT[64][64];
  int n = blockIdx.z, hh = blockIdx.y;
  int q0 = blockIdx.x * 64;
  int t = threadIdx.x;
  const float* base = qkv + (size_t)n * 1024 * 3072;

  for (int e = t; e < 4096; e += 256) {
    int i = e >> 6, c = e & 63;
    QsT[c][i] = base[(size_t)(q0 + i) * 3072 + hh * 64 + c] * 0.125f;
  }

  int i = t >> 2;
  int g = t & 3;
  int c0 = g * 16;
  float m = -1e30f, l = 0.f;
  float o[16];
#pragma unroll
  for (int cc = 0; cc < 16; cc++) o[cc] = 0.f;
  __syncthreads();

  for (int k0 = 0; k0 < 1024; k0 += 64) {
    for (int e = t; e < 4096; e += 256) {
      int j = e >> 6, c = e & 63;
      KVs[c][j] = base[(size_t)(k0 + j) * 3072 + 1024 + hh * 64 + c];
    }
    __syncthreads();

    float s[16];
#pragma unroll
    for (int jj = 0; jj < 16; jj++) s[jj] = 0.f;
#pragma unroll 4
    for (int c = 0; c < 64; c++) {
      float qv = QsT[c][i];
#pragma unroll
      for (int jj = 0; jj < 16; jj++) s[jj] += qv * KVs[c][g + jj * 4];
    }

    float mt = s[0];
#pragma unroll
    for (int jj = 1; jj < 16; jj++) mt = fmaxf(mt, s[jj]);
    mt = fmaxf(mt, __shfl_xor_sync(0xffffffffu, mt, 1));
    mt = fmaxf(mt, __shfl_xor_sync(0xffffffffu, mt, 2));
    float mn = fmaxf(m, mt);
    float alpha = __expf(m - mn);
    float lt = 0.f;
#pragma unroll
    for (int jj = 0; jj < 16; jj++) {
      s[jj] = __expf(s[jj] - mn);
      lt += s[jj];
    }
    lt += __shfl_xor_sync(0xffffffffu, lt, 1);
    lt += __shfl_xor_sync(0xffffffffu, lt, 2);
    l = l * alpha + lt;
    m = mn;
#pragma unroll
    for (int cc = 0; cc < 16; cc++) o[cc] *= alpha;
#pragma unroll
    for (int jj = 0; jj < 16; jj++) PsT[g + jj * 4][i] = s[jj];
    __syncthreads();

    for (int e = t; e < 4096; e += 256) {
      int j = e >> 6, c = e & 63;
      KVs[j][c] = base[(size_t)(k0 + j) * 3072 + 2048 + hh * 64 + c];
    }
    __syncthreads();

#pragma unroll 4
    for (int j = 0; j < 64; j++) {
      float pv = PsT[j][i];
      float4 v0 = *(const float4*)&KVs[j][c0];
      float4 v1 = *(const float4*)&KVs[j][c0 + 4];
      float4 v2 = *(const float4*)&KVs[j][c0 + 8];
      float4 v3 = *(const float4*)&KVs[j][c0 + 12];
      o[0] += pv * v0.x;  o[1] += pv * v0.y;  o[2] += pv * v0.z;  o[3] += pv * v0.w;
      o[4] += pv * v1.x;  o[5] += pv * v1.y;  o[6] += pv * v1.z;  o[7] += pv * v1.w;
      o[8] += pv * v2.x;  o[9] += pv * v2.y;  o[10] += pv * v2.z; o[11] += pv * v2.w;
      o[12] += pv * v3.x; o[13] += pv * v3.y; o[14] += pv * v3.z; o[15] += pv * v3.w;
    }
    __syncthreads();
  }

  float rl = 1.f / l;
  float* orow = out + (size_t)(n * 1024 + q0 + i) * 1024 + hh * 64;
#pragma unroll
  for (int cc = 0; cc < 16; cc++) orow[c0 + cc] = o[cc] * rl;
}

// ---------------------------------------------------------------------------
extern "C" void kernel_launch(void* const* d_in, const int* in_sizes, int n_in,
                              void* d_out, int out_size) {
  const float* x      = (const float*)d_in[0];
  const float* ln1_w  = (const float*)d_in[1];
  const float* ln1_b  = (const float*)d_in[2];
  const float* in_w   = (const float*)d_in[3];
  const float* in_b   = (const float*)d_in[4];
  const float* out_w  = (const float*)d_in[5];
  const float* out_b  = (const float*)d_in[6];
  const float* ln2_w  = (const float*)d_in[7];
  const float* ln2_b  = (const float*)d_in[8];
  const float* fc_w   = (const float*)d_in[9];
  const float* fc_b   = (const float*)d_in[10];
  const float* proj_w = (const float*)d_in[11];
  const float* proj_b = (const float*)d_in[12];
  float* out = (float*)d_out;

  float *h, *qkv, *attn, *x1, *h2, *fc;
  cudaGetSymbolAddress((void**)&h, g_h);
  cudaGetSymbolAddress((void**)&qkv, g_qkv);
  cudaGetSymbolAddress((void**)&attn, g_attn);
  cudaGetSymbolAddress((void**)&x1, g_x1);
  cudaGetSymbolAddress((void**)&h2, g_h2);
  cudaGetSymbolAddress((void**)&fc, g_fc);

  // 1. LN1, write n-major
  ln_kernel<<<8192, 256>>>(x, ln1_w, ln1_b, h, 1);
  // 2. qkv = h @ in_w^T + in_b          [8192 x 3072]
  gemm_tc<0, false><<<dim3(24, 64), 256>>>(h, in_w, in_b, nullptr, qkv, 3072, 1024);
  // 3. attention -> attn (n-major)      [8192 x 1024]
  attn_kernel<<<dim3(16, 16, 8), 256>>>(qkv, attn);
  // 4. x1 = x + attn @ out_w^T + out_b  (remap to s-major)
  gemm_tc<2, true><<<dim3(8, 64), 256>>>(attn, out_w, out_b, x, x1, 1024, 1024);
  // 5. LN2
  ln_kernel<<<8192, 256>>>(x1, ln2_w, ln2_b, h2, 0);
  // 6. fc = QuickGELU(h2 @ fc_w^T + fc_b)  [8192 x 4096]
  gemm_tc<1, false><<<dim3(32, 64), 256>>>(h2, fc_w, fc_b, nullptr, fc, 4096, 1024);
  // 7. out = x1 + fc @ proj_w^T + proj_b   [8192 x 1024]
  gemm_tc<2, false><<<dim3(8, 64), 256>>>(fc, proj_w, proj_b, x1, out, 1024, 4096);
}

// round 3
// speedup vs baseline: 4.3102x; 2.6199x over previous
#include <cuda_runtime.h>
#include <math.h>
#include <stdint.h>

// ---------------------------------------------------------------------------
// ResidualAttentionBlock: x[1024,8,1024] fp32, D=1024, H=16, c=64
// All GEMM operands pre-rounded to tf32 (idempotent), so mma loops load raw
// bits. Attention is now tf32 mma with fragment-packed shared layouts.
// ---------------------------------------------------------------------------

#define NTOK 8192
#define DMODEL 1024

__device__ float g_h[NTOK * DMODEL];
__device__ float g_qkv[NTOK * 3 * DMODEL];
__device__ float g_attn[NTOK * DMODEL];
__device__ float g_x1[NTOK * DMODEL];
__device__ float g_h2[NTOK * DMODEL];
__device__ float g_fc[NTOK * 4 * DMODEL];
// tf32-rounded weight copies
__device__ float g_wq[3 * DMODEL * DMODEL];
__device__ float g_wo[DMODEL * DMODEL];
__device__ float g_wf[4 * DMODEL * DMODEL];
__device__ float g_wp[4 * DMODEL * DMODEL];

__device__ __forceinline__ float tf32f(float v) {
  uint32_t r;
  asm("cvt.rna.tf32.f32 %0, %1;" : "=r"(r) : "f"(v));
  return __uint_as_float(r);
}

// ---------------------------------------------------------------------------
// Weight pre-round (float4 grid-stride)
// ---------------------------------------------------------------------------
__global__ void __launch_bounds__(256) wcvt_kernel(const float* __restrict__ in,
                                                  float* __restrict__ out, int n4) {
  int i = blockIdx.x * 256 + threadIdx.x;
  if (i < n4) {
    float4 v = ((const float4*)in)[i];
    v.x = tf32f(v.x); v.y = tf32f(v.y); v.z = tf32f(v.z); v.w = tf32f(v.w);
    ((float4*)out)[i] = v;
  }
}

// ---------------------------------------------------------------------------
// LayerNorm (+ optional tf32 rounding of output)
// ---------------------------------------------------------------------------
__global__ void __launch_bounds__(256) ln_kernel(
    const float* __restrict__ in, const float* __restrict__ w,
    const float* __restrict__ b, float* __restrict__ out, int remap) {
  int row = blockIdx.x;
  int out_row = remap ? ((row & 7) * 1024 + (row >> 3)) : row;
  const float* xr = in + (size_t)row * DMODEL;
  int t = threadIdx.x;
  float v[4];
  float s = 0.f, ss = 0.f;
#pragma unroll
  for (int i = 0; i < 4; i++) {
    v[i] = xr[t + 256 * i];
    s += v[i];
    ss += v[i] * v[i];
  }
#pragma unroll
  for (int o = 16; o > 0; o >>= 1) {
    s += __shfl_xor_sync(0xffffffffu, s, o);
    ss += __shfl_xor_sync(0xffffffffu, ss, o);
  }
  __shared__ float rs[8], rss[8];
  int warp = t >> 5, lane = t & 31;
  if (lane == 0) { rs[warp] = s; rss[warp] = ss; }
  __syncthreads();
  if (t == 0) {
    float a = 0.f, c = 0.f;
#pragma unroll
    for (int i = 0; i < 8; i++) { a += rs[i]; c += rss[i]; }
    rs[0] = a; rss[0] = c;
  }
  __syncthreads();
  float mean = rs[0] * (1.f / 1024.f);
  float var = rss[0] * (1.f / 1024.f) - mean * mean;
  float rstd = rsqrtf(var + 1e-5f);
  float* orow = out + (size_t)out_row * DMODEL;
#pragma unroll
  for (int i = 0; i < 4; i++) {
    int c = t + 256 * i;
    orow[c] = tf32f((v[i] - mean) * rstd * w[c] + b[c]);
  }
}

// ---------------------------------------------------------------------------
// tf32 tensor-core NT GEMM (inputs pre-rounded -> no cvt in loop)
// EPI: 0 bias, 1 bias+QuickGELU, 2 bias+residual. REMAP as before.
// RND: round output to tf32 (for buffers feeding later GEMMs).
// ---------------------------------------------------------------------------
template <int EPI, bool REMAP, bool RND>
__global__ void __launch_bounds__(256) gemm_tc(
    const float* __restrict__ A, const float* __restrict__ B,
    const float* __restrict__ bias, const float* __restrict__ res,
    float* __restrict__ C, int N, int K) {
  __shared__ __align__(16) float As[2][128][20];
  __shared__ __align__(16) float Bs[2][128][20];
  int tid = threadIdx.x;
  int lane = tid & 31, warp = tid >> 5;
  int wm = warp >> 2, wn = warp & 3;
  const float* Ab = A + (size_t)blockIdx.y * 128 * K;
  const float* Bb = B + (size_t)blockIdx.x * 128 * K;

  float acc[4][4][4];
#pragma unroll
  for (int mi = 0; mi < 4; mi++)
#pragma unroll
    for (int ni = 0; ni < 4; ni++)
#pragma unroll
      for (int r = 0; r < 4; r++) acc[mi][ni][r] = 0.f;

  auto load_stage = [&](int kt, int buf) {
#pragma unroll
    for (int it = 0; it < 2; it++) {
      int task = tid + it * 256;
      int row = task >> 2, c4 = (task & 3) << 2;
      const float* sa = Ab + (size_t)row * K + kt * 16 + c4;
      const float* sb = Bb + (size_t)row * K + kt * 16 + c4;
      uint32_t da = (uint32_t)__cvta_generic_to_shared(&As[buf][row][c4]);
      uint32_t db = (uint32_t)__cvta_generic_to_shared(&Bs[buf][row][c4]);
      asm volatile("cp.async.cg.shared.global [%0], [%1], 16;" ::"r"(da), "l"(sa));
      asm volatile("cp.async.cg.shared.global [%0], [%1], 16;" ::"r"(db), "l"(sb));
    }
    asm volatile("cp.async.commit_group;");
  };

  int KT = K >> 4;
  load_stage(0, 0);

  for (int kt = 0; kt < KT; kt++) {
    int buf = kt & 1;
    if (kt + 1 < KT) {
      load_stage(kt + 1, buf ^ 1);
      asm volatile("cp.async.wait_group 1;");
    } else {
      asm volatile("cp.async.wait_group 0;");
    }
    __syncthreads();

#pragma unroll
    for (int ks = 0; ks < 2; ks++) {
      uint32_t af[4][4], bf[4][2];
      int ar = lane >> 2;
      int ac = ks * 8 + (lane & 3);
#pragma unroll
      for (int mi = 0; mi < 4; mi++) {
        int r = wm * 64 + mi * 16 + ar;
        af[mi][0] = __float_as_uint(As[buf][r][ac]);
        af[mi][1] = __float_as_uint(As[buf][r + 8][ac]);
        af[mi][2] = __float_as_uint(As[buf][r][ac + 4]);
        af[mi][3] = __float_as_uint(As[buf][r + 8][ac + 4]);
      }
#pragma unroll
      for (int ni = 0; ni < 4; ni++) {
        int n = wn * 32 + ni * 8 + ar;
        bf[ni][0] = __float_as_uint(Bs[buf][n][ac]);
        bf[ni][1] = __float_as_uint(Bs[buf][n][ac + 4]);
      }
#pragma unroll
      for (int mi = 0; mi < 4; mi++)
#pragma unroll
        for (int ni = 0; ni < 4; ni++) {
          asm volatile(
              "mma.sync.aligned.m16n8k8.row.col.f32.tf32.tf32.f32 "
              "{%0,%1,%2,%3}, {%4,%5,%6,%7}, {%8,%9}, {%0,%1,%2,%3};"
              : "+f"(acc[mi][ni][0]), "+f"(acc[mi][ni][1]),
                "+f"(acc[mi][ni][2]), "+f"(acc[mi][ni][3])
              : "r"(af[mi][0]), "r"(af[mi][1]), "r"(af[mi][2]), "r"(af[mi][3]),
                "r"(bf[ni][0]), "r"(bf[ni][1]));
        }
    }
    __syncthreads();
  }

#pragma unroll
  for (int mi = 0; mi < 4; mi++) {
#pragma unroll
    for (int half = 0; half < 2; half++) {
      int r = blockIdx.y * 128 + wm * 64 + mi * 16 + (lane >> 2) + half * 8;
      int om = REMAP ? ((r & 1023) * 8 + (r >> 10)) : r;
      float* crow = C + (size_t)om * N;
      const float* rrow = (EPI == 2) ? res + (size_t)om * N : nullptr;
#pragma unroll
      for (int ni = 0; ni < 4; ni++) {
        int cix = blockIdx.x * 128 + wn * 32 + ni * 8 + (lane & 3) * 2;
        float v0 = acc[mi][ni][half * 2 + 0] + bias[cix];
        float v1 = acc[mi][ni][half * 2 + 1] + bias[cix + 1];
        if (EPI == 1) {
          v0 = v0 * (1.f / (1.f + __expf(-1.702f * v0)));
          v1 = v1 * (1.f / (1.f + __expf(-1.702f * v1)));
        }
        if (EPI == 2) {
          v0 += rrow[cix];
          v1 += rrow[cix + 1];
        }
        if (RND) { v0 = tf32f(v0); v1 = tf32f(v1); }
        *(float2*)&crow[cix] = make_float2(v0, v1);
      }
    }
  }
}

// ---------------------------------------------------------------------------
// tf32 MMA flash attention.
// Block: 256 thr (8 warps), q-tile 128 (16 rows/warp), grid (8, 16, 8).
// Shared (dynamic, 112 KB):
//   Qf [8 warps][8 ks][32 lane][4 reg]   A-fragment packed Q (scaled)
//   Kf [2 buf][8 nt][4 kp][32 lane][4]   B-frag packed K (kp packs 2 k-steps)
//   Vf [8 nt][4 kp][32 lane][4]          B-frag packed V
//   Pf [8 warps][8 ks][32 lane][4]       A-frag packed P (warp-private)
// Per mma operand = one conflict-free LDS.128. No cvt (qkv pre-rounded).
// ---------------------------------------------------------------------------
__device__ __forceinline__ void mma8(float* d, const float4& a, float b0, float b1) {
  asm volatile(
      "mma.sync.aligned.m16n8k8.row.col.f32.tf32.tf32.f32 "
      "{%0,%1,%2,%3}, {%4,%5,%6,%7}, {%8,%9}, {%0,%1,%2,%3};"
      : "+f"(d[0]), "+f"(d[1]), "+f"(d[2]), "+f"(d[3])
      : "r"(__float_as_uint(a.x)), "r"(__float_as_uint(a.y)),
        "r"(__float_as_uint(a.z)), "r"(__float_as_uint(a.w)),
        "r"(__float_as_uint(b0)), "r"(__float_as_uint(b1)));
}

__global__ void __launch_bounds__(256) attn_mma(const float* __restrict__ qkv,
                                                float* __restrict__ out) {
  extern __shared__ float sm[];
  float* Qf = sm;           // 8192 floats
  float* KfA = sm + 8192;   // 4096
  float* KfB = sm + 12288;  // 4096
  float* Vf = sm + 16384;   // 4096
  float* Pf = sm + 20480;   // 8192

  int tid = threadIdx.x, lane = tid & 31, w = tid >> 5;
  int qt = blockIdx.x, h = blockIdx.y, n = blockIdx.z;
  const float* base = qkv + (size_t)n * 1024 * 3072;
  const float* qb = base + h * 64;
  const float* kb = base + 1024 + h * 64;
  const float* vb = base + 2048 + h * 64;

  // ---- Q -> Qf (A-frag packed, scaled by 1/sqrt(64); scale exact on tf32) ----
#pragma unroll
  for (int j = 0; j < 8; j++) {
    int e = tid + j * 256;
    int row = e >> 4, c0 = (e & 15) << 2;
    float4 q = *(const float4*)(qb + (size_t)(qt * 128 + row) * 3072 + c0);
    int wq = row >> 4, rl = row & 15;
    int idx = wq * 1024 + ((c0 >> 3) * 32 + (rl & 7) * 4) * 4 + (rl >> 3) + ((c0 >> 2) & 1) * 2;
    Qf[idx] = q.x * 0.125f;
    Qf[idx + 4] = q.y * 0.125f;
    Qf[idx + 8] = q.z * 0.125f;
    Qf[idx + 12] = q.w * 0.125f;
  }

  // ---- prefetch + stage K tile 0 into KfA ----
  float4 ka[4];
#pragma unroll
  for (int j = 0; j < 4; j++) {
    int e = tid + j * 256;
    int key = e >> 4, c0 = (e & 15) << 2;
    ka[j] = *(const float4*)(kb + (size_t)key * 3072 + c0);
  }
#pragma unroll
  for (int j = 0; j < 4; j++) {
    int e = tid + j * 256;
    int key = e >> 4, c0 = (e & 15) << 2;
    int nt = key >> 3, ks = c0 >> 3;
    int idx = ((nt * 4 + (ks >> 1)) * 32 + (key & 7) * 4) * 4 + (ks & 1) * 2 + ((c0 >> 2) & 1);
    KfA[idx] = ka[j].x; KfA[idx + 4] = ka[j].y;
    KfA[idx + 8] = ka[j].z; KfA[idx + 12] = ka[j].w;
  }
  __syncthreads();

  float m0 = -1e30f, m1 = -1e30f, l0 = 0.f, l1 = 0.f;
  float o[8][4];
#pragma unroll
  for (int nt = 0; nt < 8; nt++)
#pragma unroll
    for (int r = 0; r < 4; r++) o[nt][r] = 0.f;

  float* Pw = Pf + w * 1024;
  const float4* Qr = (const float4*)(Qf + w * 1024);
  const float4* Pr = (const float4*)(Pf + w * 1024);
  const float4* Vr = (const float4*)Vf;

  int kl0 = (lane & 3) * 2;
  int dl0 = (lane >> 2) * 4 + (kl0 & 3);
  int dl1 = (lane >> 2) * 4 + ((kl0 + 1) & 3);
  int rb0 = ((kl0 >> 2) & 1) * 2;
  int rb1 = (((kl0 + 1) >> 2) & 1) * 2;

  for (int kt = 0; kt < 16; kt++) {
    float* Kcur = (kt & 1) ? KfB : KfA;
    float* Knxt = (kt & 1) ? KfA : KfB;

    // prefetch V(kt) and K(kt+1) into registers
    float4 va[4];
#pragma unroll
    for (int j = 0; j < 4; j++) {
      int e = tid + j * 256;
      int key = e >> 4, c0 = (e & 15) << 2;
      va[j] = *(const float4*)(vb + (size_t)(kt * 64 + key) * 3072 + c0);
      if (kt < 15)
        ka[j] = *(const float4*)(kb + (size_t)((kt + 1) * 64 + key) * 3072 + c0);
    }

    // ---- S = Q K^T ----
    float s[8][4];
#pragma unroll
    for (int nt = 0; nt < 8; nt++)
#pragma unroll
      for (int r = 0; r < 4; r++) s[nt][r] = 0.f;
    const float4* Kr = (const float4*)Kcur;
#pragma unroll
    for (int kp = 0; kp < 4; kp++) {
      float4 a0 = Qr[(kp * 2) * 32 + lane];
      float4 a1 = Qr[(kp * 2 + 1) * 32 + lane];
#pragma unroll
      for (int nt = 0; nt < 8; nt++) {
        float4 b = Kr[(nt * 4 + kp) * 32 + lane];
        mma8(s[nt], a0, b.x, b.y);
        mma8(s[nt], a1, b.z, b.w);
      }
    }

    // ---- online softmax (rows r=lane>>2 and r+8) ----
    float mx0 = -1e30f, mx1 = -1e30f;
#pragma unroll
    for (int nt = 0; nt < 8; nt++) {
      mx0 = fmaxf(mx0, fmaxf(s[nt][0], s[nt][1]));
      mx1 = fmaxf(mx1, fmaxf(s[nt][2], s[nt][3]));
    }
    mx0 = fmaxf(mx0, __shfl_xor_sync(0xffffffffu, mx0, 1));
    mx0 = fmaxf(mx0, __shfl_xor_sync(0xffffffffu, mx0, 2));
    mx1 = fmaxf(mx1, __shfl_xor_sync(0xffffffffu, mx1, 1));
    mx1 = fmaxf(mx1, __shfl_xor_sync(0xffffffffu, mx1, 2));
    float mn0 = fmaxf(m0, mx0), mn1 = fmaxf(m1, mx1);
    float a0s = __expf(m0 - mn0), a1s = __expf(m1 - mn1);
    float ls0 = 0.f, ls1 = 0.f;
#pragma unroll
    for (int nt = 0; nt < 8; nt++) {
      float p00 = __expf(s[nt][0] - mn0);
      float p01 = __expf(s[nt][1] - mn0);
      float p10 = __expf(s[nt][2] - mn1);
      float p11 = __expf(s[nt][3] - mn1);
      ls0 += p00 + p01;
      ls1 += p10 + p11;
      Pw[(nt * 32 + dl0) * 4 + rb0] = tf32f(p00);
      Pw[(nt * 32 + dl1) * 4 + rb1] = tf32f(p01);
      Pw[(nt * 32 + dl0) * 4 + rb0 + 1] = tf32f(p10);
      Pw[(nt * 32 + dl1) * 4 + rb1 + 1] = tf32f(p11);
    }
    ls0 += __shfl_xor_sync(0xffffffffu, ls0, 1);
    ls0 += __shfl_xor_sync(0xffffffffu, ls0, 2);
    ls1 += __shfl_xor_sync(0xffffffffu, ls1, 1);
    ls1 += __shfl_xor_sync(0xffffffffu, ls1, 2);
    l0 = l0 * a0s + ls0;
    l1 = l1 * a1s + ls1;
    m0 = mn0; m1 = mn1;
#pragma unroll
    for (int nt = 0; nt < 8; nt++) {
      o[nt][0] *= a0s; o[nt][1] *= a0s;
      o[nt][2] *= a1s; o[nt][3] *= a1s;
    }
    __syncwarp();

    // ---- stage V(kt) ----
#pragma unroll
    for (int j = 0; j < 4; j++) {
      int e = tid + j * 256;
      int key = e >> 4, c0 = (e & 15) << 2;
      int nt = c0 >> 3, ks = key >> 3;
      int idx = ((nt * 4 + (ks >> 1)) * 32 + (c0 & 7) * 4 + (key & 3)) * 4 +
                (ks & 1) * 2 + ((key >> 2) & 1);
      Vf[idx] = va[j].x; Vf[idx + 16] = va[j].y;
      Vf[idx + 32] = va[j].z; Vf[idx + 48] = va[j].w;
    }
    __syncthreads();  // Vf ready; all warps past S-phase

    // ---- O += P V ----
#pragma unroll
    for (int kp = 0; kp < 4; kp++) {
      float4 a0 = Pr[(kp * 2) * 32 + lane];
      float4 a1 = Pr[(kp * 2 + 1) * 32 + lane];
#pragma unroll
      for (int nt = 0; nt < 8; nt++) {
        float4 b = Vr[(nt * 4 + kp) * 32 + lane];
        mma8(o[nt], a0, b.x, b.y);
        mma8(o[nt], a1, b.z, b.w);
      }
    }

    // ---- stage K(kt+1) ----
    if (kt < 15) {
#pragma unroll
      for (int j = 0; j < 4; j++) {
        int e = tid + j * 256;
        int key = e >> 4, c0 = (e & 15) << 2;
        int nt = key >> 3, ks = c0 >> 3;
        int idx = ((nt * 4 + (ks >> 1)) * 32 + (key & 7) * 4) * 4 + (ks & 1) * 2 + ((c0 >> 2) & 1);
        Knxt[idx] = ka[j].x; Knxt[idx + 4] = ka[j].y;
        Knxt[idx + 8] = ka[j].z; Knxt[idx + 12] = ka[j].w;
      }
    }
    __syncthreads();  // next iter may reuse Vf / read Knxt
  }

  // ---- output (rounded to tf32; feeds out-proj GEMM) ----
  float rl0 = 1.f / l0, rl1 = 1.f / l1;
  int row0 = qt * 128 + w * 16 + (lane >> 2);
  float* o0 = out + ((size_t)(n * 1024 + row0)) * 1024 + h * 64;
  float* o1 = o0 + 8 * 1024;
#pragma unroll
  for (int nt = 0; nt < 8; nt++) {
    int c = nt * 8 + (lane & 3) * 2;
    *(float2*)(o0 + c) = make_float2(tf32f(o[nt][0] * rl0), tf32f(o[nt][1] * rl0));
    *(float2*)(o1 + c) = make_float2(tf32f(o[nt][2] * rl1), tf32f(o[nt][3] * rl1));
  }
}

// ---------------------------------------------------------------------------
extern "C" void kernel_launch(void* const* d_in, const int* in_sizes, int n_in,
                              void* d_out, int out_size) {
  const float* x      = (const float*)d_in[0];
  const float* ln1_w  = (const float*)d_in[1];
  const float* ln1_b  = (const float*)d_in[2];
  const float* in_w   = (const float*)d_in[3];
  const float* in_b   = (const float*)d_in[4];
  const float* out_w  = (const float*)d_in[5];
  const float* out_b  = (const float*)d_in[6];
  const float* ln2_w  = (const float*)d_in[7];
  const float* ln2_b  = (const float*)d_in[8];
  const float* fc_w   = (const float*)d_in[9];
  const float* fc_b   = (const float*)d_in[10];
  const float* proj_w = (const float*)d_in[11];
  const float* proj_b = (const float*)d_in[12];
  float* out = (float*)d_out;

  float *h, *qkv, *attn, *x1, *h2, *fc, *wq, *wo, *wf, *wp;
  cudaGetSymbolAddress((void**)&h, g_h);
  cudaGetSymbolAddress((void**)&qkv, g_qkv);
  cudaGetSymbolAddress((void**)&attn, g_attn);
  cudaGetSymbolAddress((void**)&x1, g_x1);
  cudaGetSymbolAddress((void**)&h2, g_h2);
  cudaGetSymbolAddress((void**)&fc, g_fc);
  cudaGetSymbolAddress((void**)&wq, g_wq);
  cudaGetSymbolAddress((void**)&wo, g_wo);
  cudaGetSymbolAddress((void**)&wf, g_wf);
  cudaGetSymbolAddress((void**)&wp, g_wp);

  static int smem_set = 0;
  if (!smem_set) {
    cudaFuncSetAttribute(attn_mma, cudaFuncAttributeMaxDynamicSharedMemorySize, 114688);
    smem_set = 1;
  }

  // 0. weight pre-round to tf32
  wcvt_kernel<<<3072, 256>>>(in_w, wq, 3 * 1024 * 1024 / 4);
  wcvt_kernel<<<1024, 256>>>(out_w, wo, 1024 * 1024 / 4);
  wcvt_kernel<<<4096, 256>>>(fc_w, wf, 4 * 1024 * 1024 / 4);
  wcvt_kernel<<<4096, 256>>>(proj_w, wp, 4 * 1024 * 1024 / 4);

  // 1. LN1, write n-major (tf32-rounded)
  ln_kernel<<<8192, 256>>>(x, ln1_w, ln1_b, h, 1);
  // 2. qkv = h @ in_w^T + in_b (rounded; feeds attention)
  gemm_tc<0, false, true><<<dim3(24, 64), 256>>>(h, wq, in_b, nullptr, qkv, 3072, 1024);
  // 3. attention -> attn (n-major, rounded)
  attn_mma<<<dim3(8, 16, 8), 256, 114688>>>(qkv, attn);
  // 4. x1 = x + attn @ out_w^T + out_b (fp32, remap to s-major)
  gemm_tc<2, true, false><<<dim3(8, 64), 256>>>(attn, wo, out_b, x, x1, 1024, 1024);
  // 5. LN2 (rounded)
  ln_kernel<<<8192, 256>>>(x1, ln2_w, ln2_b, h2, 0);
  // 6. fc = QuickGELU(h2 @ fc_w^T + fc_b) (rounded)
  gemm_tc<1, false, true><<<dim3(32, 64), 256>>>(h2, wf, fc_b, nullptr, fc, 4096, 1024);
  // 7. out = x1 + fc @ proj_w^T + proj_b (fp32)
  gemm_tc<2, false, false><<<dim3(8, 64), 256>>>(fc, wp, proj_b, x1, out, 1024, 4096);
}

// round 4
// speedup vs baseline: 5.0716x; 1.1766x over previous
#include <cuda_runtime.h>
#include <math.h>
#include <stdint.h>

// ---------------------------------------------------------------------------
// ResidualAttentionBlock: x[1024,8,1024] fp32, D=1024, H=16, c=64
// GEMMs: tf32 mma, weights pre-packed into B-fragment global layout.
// Attention: tf32 mma flash kernel (fragment-packed shared).
// ---------------------------------------------------------------------------

#define NTOK 8192
#define DMODEL 1024

__device__ float g_h[NTOK * DMODEL];
__device__ float g_qkv[NTOK * 3 * DMODEL];
__device__ float g_attn[NTOK * DMODEL];
__device__ float g_x1[NTOK * DMODEL];
__device__ float g_h2[NTOK * DMODEL];
__device__ float g_fc[NTOK * 4 * DMODEL];
// tf32-rounded, B-fragment-packed weight copies
__device__ float g_wq[3 * DMODEL * DMODEL];
__device__ float g_wo[DMODEL * DMODEL];
__device__ float g_wf[4 * DMODEL * DMODEL];
__device__ float g_wp[4 * DMODEL * DMODEL];

__device__ __forceinline__ float tf32f(float v) {
  uint32_t r;
  asm("cvt.rna.tf32.f32 %0, %1;" : "=r"(r) : "f"(v));
  return __uint_as_float(r);
}

// ---------------------------------------------------------------------------
// Weight pack: W[n][k] row-major -> W'[kt][tileN][ks][lane][2] fragment order.
//   n = tileN*8 + (lane>>2), k = kt*16 + ks*8 + (lane&3) (+4 for second elem)
// One thread per output float2. NT8 = N/8.
// ---------------------------------------------------------------------------
__global__ void __launch_bounds__(256) wpack_kernel(
    const float* __restrict__ W, float* __restrict__ Wp, int NT8, int K, int total) {
  int idx = blockIdx.x * 256 + threadIdx.x;
  if (idx >= total) return;
  int lane = idx & 31;
  int ks = (idx >> 5) & 1;
  int t2 = idx >> 6;
  int tileN = t2 % NT8;
  int kt = t2 / NT8;
  int n = tileN * 8 + (lane >> 2);
  int k = kt * 16 + ks * 8 + (lane & 3);
  const float* src = W + (size_t)n * K + k;
  float2 v = make_float2(tf32f(src[0]), tf32f(src[4]));
  *(float2*)(Wp + (size_t)idx * 2) = v;
}

// ---------------------------------------------------------------------------
// LayerNorm (tf32-rounded output)
// ---------------------------------------------------------------------------
__global__ void __launch_bounds__(256) ln_kernel(
    const float* __restrict__ in, const float* __restrict__ w,
    const float* __restrict__ b, float* __restrict__ out, int remap) {
  int row = blockIdx.x;
  int out_row = remap ? ((row & 7) * 1024 + (row >> 3)) : row;
  const float* xr = in + (size_t)row * DMODEL;
  int t = threadIdx.x;
  float v[4];
  float s = 0.f, ss = 0.f;
#pragma unroll
  for (int i = 0; i < 4; i++) {
    v[i] = xr[t + 256 * i];
    s += v[i];
    ss += v[i] * v[i];
  }
#pragma unroll
  for (int o = 16; o > 0; o >>= 1) {
    s += __shfl_xor_sync(0xffffffffu, s, o);
    ss += __shfl_xor_sync(0xffffffffu, ss, o);
  }
  __shared__ float rs[8], rss[8];
  int warp = t >> 5, lane = t & 31;
  if (lane == 0) { rs[warp] = s; rss[warp] = ss; }
  __syncthreads();
  if (t == 0) {
    float a = 0.f, c = 0.f;
#pragma unroll
    for (int i = 0; i < 8; i++) { a += rs[i]; c += rss[i]; }
    rs[0] = a; rss[0] = c;
  }
  __syncthreads();
  float mean = rs[0] * (1.f / 1024.f);
  float var = rss[0] * (1.f / 1024.f) - mean * mean;
  float rstd = rsqrtf(var + 1e-5f);
  float* orow = out + (size_t)out_row * DMODEL;
#pragma unroll
  for (int i = 0; i < 4; i++) {
    int c = t + 256 * i;
    orow[c] = tf32f((v[i] - mean) * rstd * w[c] + b[c]);
  }
}

// ---------------------------------------------------------------------------
// tf32 NT GEMM v2: 128x128 block tile, 4 warps (warp tile 64x64), BK=16,
// 2-stage cp.async. A row-major (pad-20 shared, scalar frag LDS).
// B pre-packed fragment order: identity cp.async -> LDS.64 frags.
// EPI: 0 bias, 1 bias+QuickGELU, 2 bias+residual. REMAP, RND as before.
// ---------------------------------------------------------------------------
template <int EPI, bool REMAP, bool RND>
__global__ void __launch_bounds__(128) gemm_tc(
    const float* __restrict__ A, const float* __restrict__ Bp,
    const float* __restrict__ bias, const float* __restrict__ res,
    float* __restrict__ C, int N, int K) {
  __shared__ __align__(16) float As[2][128][20];
  __shared__ __align__(16) float Bs[2][2048];
  int tid = threadIdx.x;
  int lane = tid & 31, warp = tid >> 5;
  int wm = warp >> 1, wn = warp & 1;
  const float* Ab = A + (size_t)blockIdx.y * 128 * K;
  int NT8 = N >> 3;
  // block's B chunk for k-tile kt starts at (kt*NT8 + blockIdx.x*16)*128 floats
  const float* Bb = Bp + (size_t)blockIdx.x * 16 * 128;

  float acc[4][8][4];
#pragma unroll
  for (int mi = 0; mi < 4; mi++)
#pragma unroll
    for (int ni = 0; ni < 8; ni++)
#pragma unroll
      for (int r = 0; r < 4; r++) acc[mi][ni][r] = 0.f;

  auto load_stage = [&](int kt, int buf) {
    const float* Bsrc = Bb + (size_t)kt * NT8 * 128;
#pragma unroll
    for (int it = 0; it < 4; it++) {
      int task = tid + it * 128;
      int row = task >> 2, c4 = (task & 3) << 2;
      const float* sa = Ab + (size_t)row * K + kt * 16 + c4;
      uint32_t da = (uint32_t)__cvta_generic_to_shared(&As[buf][row][c4]);
      asm volatile("cp.async.cg.shared.global [%0], [%1], 16;" ::"r"(da), "l"(sa));
      const float* sb = Bsrc + task * 4;
      uint32_t db = (uint32_t)__cvta_generic_to_shared(&Bs[buf][task * 4]);
      asm volatile("cp.async.cg.shared.global [%0], [%1], 16;" ::"r"(db), "l"(sb));
    }
    asm volatile("cp.async.commit_group;");
  };

  int KT = K >> 4;
  load_stage(0, 0);

  for (int kt = 0; kt < KT; kt++) {
    int buf = kt & 1;
    if (kt + 1 < KT) {
      load_stage(kt + 1, buf ^ 1);
      asm volatile("cp.async.wait_group 1;");
    } else {
      asm volatile("cp.async.wait_group 0;");
    }
    __syncthreads();

#pragma unroll
    for (int ks = 0; ks < 2; ks++) {
      uint32_t af[4][4];
      float2 bf[8];
      int ar = lane >> 2;
      int ac = ks * 8 + (lane & 3);
#pragma unroll
      for (int mi = 0; mi < 4; mi++) {
        int r = wm * 64 + mi * 16 + ar;
        af[mi][0] = __float_as_uint(As[buf][r][ac]);
        af[mi][1] = __float_as_uint(As[buf][r + 8][ac]);
        af[mi][2] = __float_as_uint(As[buf][r][ac + 4]);
        af[mi][3] = __float_as_uint(As[buf][r + 8][ac + 4]);
      }
#pragma unroll
      for (int ni = 0; ni < 8; ni++)
        bf[ni] = *(const float2*)&Bs[buf][(((wn * 8 + ni) * 2 + ks) * 32 + lane) * 2];
#pragma unroll
      for (int mi = 0; mi < 4; mi++)
#pragma unroll
        for (int ni = 0; ni < 8; ni++) {
          asm volatile(
              "mma.sync.aligned.m16n8k8.row.col.f32.tf32.tf32.f32 "
              "{%0,%1,%2,%3}, {%4,%5,%6,%7}, {%8,%9}, {%0,%1,%2,%3};"
              : "+f"(acc[mi][ni][0]), "+f"(acc[mi][ni][1]),
                "+f"(acc[mi][ni][2]), "+f"(acc[mi][ni][3])
              : "r"(af[mi][0]), "r"(af[mi][1]), "r"(af[mi][2]), "r"(af[mi][3]),
                "r"(__float_as_uint(bf[ni].x)), "r"(__float_as_uint(bf[ni].y)));
        }
    }
    __syncthreads();
  }

#pragma unroll
  for (int mi = 0; mi < 4; mi++) {
#pragma unroll
    for (int half = 0; half < 2; half++) {
      int r = blockIdx.y * 128 + wm * 64 + mi * 16 + (lane >> 2) + half * 8;
      int om = REMAP ? ((r & 1023) * 8 + (r >> 10)) : r;
      float* crow = C + (size_t)om * N;
      const float* rrow = (EPI == 2) ? res + (size_t)om * N : nullptr;
#pragma unroll
      for (int ni = 0; ni < 8; ni++) {
        int cix = blockIdx.x * 128 + wn * 64 + ni * 8 + (lane & 3) * 2;
        float v0 = acc[mi][ni][half * 2 + 0] + bias[cix];
        float v1 = acc[mi][ni][half * 2 + 1] + bias[cix + 1];
        if (EPI == 1) {
          v0 = v0 * (1.f / (1.f + __expf(-1.702f * v0)));
          v1 = v1 * (1.f / (1.f + __expf(-1.702f * v1)));
        }
        if (EPI == 2) {
          v0 += rrow[cix];
          v1 += rrow[cix + 1];
        }
        if (RND) { v0 = tf32f(v0); v1 = tf32f(v1); }
        *(float2*)&crow[cix] = make_float2(v0, v1);
      }
    }
  }
}

// ---------------------------------------------------------------------------
// tf32 MMA flash attention (unchanged from R3).
// ---------------------------------------------------------------------------
__device__ __forceinline__ void mma8(float* d, const float4& a, float b0, float b1) {
  asm volatile(
      "mma.sync.aligned.m16n8k8.row.col.f32.tf32.tf32.f32 "
      "{%0,%1,%2,%3}, {%4,%5,%6,%7}, {%8,%9}, {%0,%1,%2,%3};"
      : "+f"(d[0]), "+f"(d[1]), "+f"(d[2]), "+f"(d[3])
      : "r"(__float_as_uint(a.x)), "r"(__float_as_uint(a.y)),
        "r"(__float_as_uint(a.z)), "r"(__float_as_uint(a.w)),
        "r"(__float_as_uint(b0)), "r"(__float_as_uint(b1)));
}

__global__ void __launch_bounds__(256) attn_mma(const float* __restrict__ qkv,
                                                float* __restrict__ out) {
  extern __shared__ float sm[];
  float* Qf = sm;           // 8192 floats
  float* KfA = sm + 8192;   // 4096
  float* KfB = sm + 12288;  // 4096
  float* Vf = sm + 16384;   // 4096
  float* Pf = sm + 20480;   // 8192

  int tid = threadIdx.x, lane = tid & 31, w = tid >> 5;
  int qt = blockIdx.x, h = blockIdx.y, n = blockIdx.z;
  const float* base = qkv + (size_t)n * 1024 * 3072;
  const float* qb = base + h * 64;
  const float* kb = base + 1024 + h * 64;
  const float* vb = base + 2048 + h * 64;

#pragma unroll
  for (int j = 0; j < 8; j++) {
    int e = tid + j * 256;
    int row = e >> 4, c0 = (e & 15) << 2;
    float4 q = *(const float4*)(qb + (size_t)(qt * 128 + row) * 3072 + c0);
    int wq = row >> 4, rl = row & 15;
    int idx = wq * 1024 + ((c0 >> 3) * 32 + (rl & 7) * 4) * 4 + (rl >> 3) + ((c0 >> 2) & 1) * 2;
    Qf[idx] = q.x * 0.125f;
    Qf[idx + 4] = q.y * 0.125f;
    Qf[idx + 8] = q.z * 0.125f;
    Qf[idx + 12] = q.w * 0.125f;
  }

  float4 ka[4];
#pragma unroll
  for (int j = 0; j < 4; j++) {
    int e = tid + j * 256;
    int key = e >> 4, c0 = (e & 15) << 2;
    ka[j] = *(const float4*)(kb + (size_t)key * 3072 + c0);
  }
#pragma unroll
  for (int j = 0; j < 4; j++) {
    int e = tid + j * 256;
    int key = e >> 4, c0 = (e & 15) << 2;
    int nt = key >> 3, ks = c0 >> 3;
    int idx = ((nt * 4 + (ks >> 1)) * 32 + (key & 7) * 4) * 4 + (ks & 1) * 2 + ((c0 >> 2) & 1);
    KfA[idx] = ka[j].x; KfA[idx + 4] = ka[j].y;
    KfA[idx + 8] = ka[j].z; KfA[idx + 12] = ka[j].w;
  }
  __syncthreads();

  float m0 = -1e30f, m1 = -1e30f, l0 = 0.f, l1 = 0.f;
  float o[8][4];
#pragma unroll
  for (int nt = 0; nt < 8; nt++)
#pragma unroll
    for (int r = 0; r < 4; r++) o[nt][r] = 0.f;

  float* Pw = Pf + w * 1024;
  const float4* Qr = (const float4*)(Qf + w * 1024);
  const float4* Pr = (const float4*)(Pf + w * 1024);
  const float4* Vr = (const float4*)Vf;

  int kl0 = (lane & 3) * 2;
  int dl0 = (lane >> 2) * 4 + (kl0 & 3);
  int dl1 = (lane >> 2) * 4 + ((kl0 + 1) & 3);
  int rb0 = ((kl0 >> 2) & 1) * 2;
  int rb1 = (((kl0 + 1) >> 2) & 1) * 2;

  for (int kt = 0; kt < 16; kt++) {
    float* Kcur = (kt & 1) ? KfB : KfA;
    float* Knxt = (kt & 1) ? KfA : KfB;

    float4 va[4];
#pragma unroll
    for (int j = 0; j < 4; j++) {
      int e = tid + j * 256;
      int key = e >> 4, c0 = (e & 15) << 2;
      va[j] = *(const float4*)(vb + (size_t)(kt * 64 + key) * 3072 + c0);
      if (kt < 15)
        ka[j] = *(const float4*)(kb + (size_t)((kt + 1) * 64 + key) * 3072 + c0);
    }

    float s[8][4];
#pragma unroll
    for (int nt = 0; nt < 8; nt++)
#pragma unroll
      for (int r = 0; r < 4; r++) s[nt][r] = 0.f;
    const float4* Kr = (const float4*)Kcur;
#pragma unroll
    for (int kp = 0; kp < 4; kp++) {
      float4 a0 = Qr[(kp * 2) * 32 + lane];
      float4 a1 = Qr[(kp * 2 + 1) * 32 + lane];
#pragma unroll
      for (int nt = 0; nt < 8; nt++) {
        float4 b = Kr[(nt * 4 + kp) * 32 + lane];
        mma8(s[nt], a0, b.x, b.y);
        mma8(s[nt], a1, b.z, b.w);
      }
    }

    float mx0 = -1e30f, mx1 = -1e30f;
#pragma unroll
    for (int nt = 0; nt < 8; nt++) {
      mx0 = fmaxf(mx0, fmaxf(s[nt][0], s[nt][1]));
      mx1 = fmaxf(mx1, fmaxf(s[nt][2], s[nt][3]));
    }
    mx0 = fmaxf(mx0, __shfl_xor_sync(0xffffffffu, mx0, 1));
    mx0 = fmaxf(mx0, __shfl_xor_sync(0xffffffffu, mx0, 2));
    mx1 = fmaxf(mx1, __shfl_xor_sync(0xffffffffu, mx1, 1));
    mx1 = fmaxf(mx1, __shfl_xor_sync(0xffffffffu, mx1, 2));
    float mn0 = fmaxf(m0, mx0), mn1 = fmaxf(m1, mx1);
    float a0s = __expf(m0 - mn0), a1s = __expf(m1 - mn1);
    float ls0 = 0.f, ls1 = 0.f;
#pragma unroll
    for (int nt = 0; nt < 8; nt++) {
      float p00 = __expf(s[nt][0] - mn0);
      float p01 = __expf(s[nt][1] - mn0);
      float p10 = __expf(s[nt][2] - mn1);
      float p11 = __expf(s[nt][3] - mn1);
      ls0 += p00 + p01;
      ls1 += p10 + p11;
      Pw[(nt * 32 + dl0) * 4 + rb0] = tf32f(p00);
      Pw[(nt * 32 + dl1) * 4 + rb1] = tf32f(p01);
      Pw[(nt * 32 + dl0) * 4 + rb0 + 1] = tf32f(p10);
      Pw[(nt * 32 + dl1) * 4 + rb1 + 1] = tf32f(p11);
    }
    ls0 += __shfl_xor_sync(0xffffffffu, ls0, 1);
    ls0 += __shfl_xor_sync(0xffffffffu, ls0, 2);
    ls1 += __shfl_xor_sync(0xffffffffu, ls1, 1);
    ls1 += __shfl_xor_sync(0xffffffffu, ls1, 2);
    l0 = l0 * a0s + ls0;
    l1 = l1 * a1s + ls1;
    m0 = mn0; m1 = mn1;
#pragma unroll
    for (int nt = 0; nt < 8; nt++) {
      o[nt][0] *= a0s; o[nt][1] *= a0s;
      o[nt][2] *= a1s; o[nt][3] *= a1s;
    }
    __syncwarp();

#pragma unroll
    for (int j = 0; j < 4; j++) {
      int e = tid + j * 256;
      int key = e >> 4, c0 = (e & 15) << 2;
      int nt = c0 >> 3, ks = key >> 3;
      int idx = ((nt * 4 + (ks >> 1)) * 32 + (c0 & 7) * 4 + (key & 3)) * 4 +
                (ks & 1) * 2 + ((key >> 2) & 1);
      Vf[idx] = va[j].x; Vf[idx + 16] = va[j].y;
      Vf[idx + 32] = va[j].z; Vf[idx + 48] = va[j].w;
    }
    __syncthreads();

#pragma unroll
    for (int kp = 0; kp < 4; kp++) {
      float4 a0 = Pr[(kp * 2) * 32 + lane];
      float4 a1 = Pr[(kp * 2 + 1) * 32 + lane];
#pragma unroll
      for (int nt = 0; nt < 8; nt++) {
        float4 b = Vr[(nt * 4 + kp) * 32 + lane];
        mma8(o[nt], a0, b.x, b.y);
        mma8(o[nt], a1, b.z, b.w);
      }
    }

    if (kt < 15) {
#pragma unroll
      for (int j = 0; j < 4; j++) {
        int e = tid + j * 256;
        int key = e >> 4, c0 = (e & 15) << 2;
        int nt = key >> 3, ks = c0 >> 3;
        int idx = ((nt * 4 + (ks >> 1)) * 32 + (key & 7) * 4) * 4 + (ks & 1) * 2 + ((c0 >> 2) & 1);
        Knxt[idx] = ka[j].x; Knxt[idx + 4] = ka[j].y;
        Knxt[idx + 8] = ka[j].z; Knxt[idx + 12] = ka[j].w;
      }
    }
    __syncthreads();
  }

  float rl0 = 1.f / l0, rl1 = 1.f / l1;
  int row0 = qt * 128 + w * 16 + (lane >> 2);
  float* o0 = out + ((size_t)(n * 1024 + row0)) * 1024 + h * 64;
  float* o1 = o0 + 8 * 1024;
#pragma unroll
  for (int nt = 0; nt < 8; nt++) {
    int c = nt * 8 + (lane & 3) * 2;
    *(float2*)(o0 + c) = make_float2(tf32f(o[nt][0] * rl0), tf32f(o[nt][1] * rl0));
    *(float2*)(o1 + c) = make_float2(tf32f(o[nt][2] * rl1), tf32f(o[nt][3] * rl1));
  }
}

// ---------------------------------------------------------------------------
extern "C" void kernel_launch(void* const* d_in, const int* in_sizes, int n_in,
                              void* d_out, int out_size) {
  const float* x      = (const float*)d_in[0];
  const float* ln1_w  = (const float*)d_in[1];
  const float* ln1_b  = (const float*)d_in[2];
  const float* in_w   = (const float*)d_in[3];
  const float* in_b   = (const float*)d_in[4];
  const float* out_w  = (const float*)d_in[5];
  const float* out_b  = (const float*)d_in[6];
  const float* ln2_w  = (const float*)d_in[7];
  const float* ln2_b  = (const float*)d_in[8];
  const float* fc_w   = (const float*)d_in[9];
  const float* fc_b   = (const float*)d_in[10];
  const float* proj_w = (const float*)d_in[11];
  const float* proj_b = (const float*)d_in[12];
  float* out = (float*)d_out;

  float *h, *qkv, *attn, *x1, *h2, *fc, *wq, *wo, *wf, *wp;
  cudaGetSymbolAddress((void**)&h, g_h);
  cudaGetSymbolAddress((void**)&qkv, g_qkv);
  cudaGetSymbolAddress((void**)&attn, g_attn);
  cudaGetSymbolAddress((void**)&x1, g_x1);
  cudaGetSymbolAddress((void**)&h2, g_h2);
  cudaGetSymbolAddress((void**)&fc, g_fc);
  cudaGetSymbolAddress((void**)&wq, g_wq);
  cudaGetSymbolAddress((void**)&wo, g_wo);
  cudaGetSymbolAddress((void**)&wf, g_wf);
  cudaGetSymbolAddress((void**)&wp, g_wp);

  static int smem_set = 0;
  if (!smem_set) {
    cudaFuncSetAttribute(attn_mma, cudaFuncAttributeMaxDynamicSharedMemorySize, 114688);
    smem_set = 1;
  }

  // 0. weight round + fragment pack  (threads = N*K/2 each)
  wpack_kernel<<<6144, 256>>>(in_w, wq, 384, 1024, 3 * 1024 * 1024 / 2);
  wpack_kernel<<<2048, 256>>>(out_w, wo, 128, 1024, 1024 * 1024 / 2);
  wpack_kernel<<<8192, 256>>>(fc_w, wf, 512, 1024, 4 * 1024 * 1024 / 2);
  wpack_kernel<<<8192, 256>>>(proj_w, wp, 128, 4096, 4 * 1024 * 1024 / 2);

  // 1. LN1, write n-major (tf32-rounded)
  ln_kernel<<<8192, 256>>>(x, ln1_w, ln1_b, h, 1);
  // 2. qkv = h @ in_w^T + in_b (rounded; feeds attention)
  gemm_tc<0, false, true><<<dim3(24, 64), 128>>>(h, wq, in_b, nullptr, qkv, 3072, 1024);
  // 3. attention -> attn (n-major, rounded)
  attn_mma<<<dim3(8, 16, 8), 256, 114688>>>(qkv, attn);
  // 4. x1 = x + attn @ out_w^T + out_b (fp32, remap to s-major)
  gemm_tc<2, true, false><<<dim3(8, 64), 128>>>(attn, wo, out_b, x, x1, 1024, 1024);
  // 5. LN2 (rounded)
  ln_kernel<<<8192, 256>>>(x1, ln2_w, ln2_b, h2, 0);
  // 6. fc = QuickGELU(h2 @ fc_w^T + fc_b) (rounded)
  gemm_tc<1, false, true><<<dim3(32, 64), 128>>>(h2, wf, fc_b, nullptr, fc, 4096, 1024);
  // 7. out = x1 + fc @ proj_w^T + proj_b (fp32)
  gemm_tc<2, false, false><<<dim3(8, 64), 128>>>(fc, wp, proj_b, x1, out, 1024, 4096);
}

// round 6
// speedup vs baseline: 5.4354x; 1.0717x over previous
#include <cuda_runtime.h>
#include <math.h>
#include <stdint.h>

// ---------------------------------------------------------------------------
// ResidualAttentionBlock: x[1024,8,1024] fp32, D=1024, H=16, c=64
// GEMMs: tf32 mma. BOTH operands fragment-pre-packed in global memory:
//   B (weights): packed once by wpack_kernel.
//   A (activations): written in A-fragment order by each producer
//     (LN kernels, attention output, fc-GEMM epilogue).
// GEMM inner loop: identity cp.async stages + LDS.128/LDS.64 fragment reads.
// ---------------------------------------------------------------------------

#define NTOK 8192
#define DMODEL 1024

__device__ float g_h[NTOK * DMODEL];        // A-frag packed (feeds qkv gemm)
__device__ float g_qkv[NTOK * 3 * DMODEL];  // row-major n-major (feeds attn)
__device__ float g_attn[NTOK * DMODEL];     // A-frag packed (feeds out-proj)
__device__ float g_x1[NTOK * DMODEL];       // row-major s-major
__device__ float g_h2[NTOK * DMODEL];       // A-frag packed (feeds fc gemm)
__device__ float g_fc[NTOK * 4 * DMODEL];   // A-frag packed (feeds proj gemm)
__device__ float g_wq[3 * DMODEL * DMODEL];
__device__ float g_wo[DMODEL * DMODEL];
__device__ float g_wf[4 * DMODEL * DMODEL];
__device__ float g_wp[4 * DMODEL * DMODEL];

__device__ __forceinline__ float tf32f(float v) {
  uint32_t r;
  asm("cvt.rna.tf32.f32 %0, %1;" : "=r"(r) : "f"(v));
  return __uint_as_float(r);
}

// A-fragment address for element (row, col) of an M x K matrix:
// chunk [row>>7][col>>4] of 2048 floats; inside:
//   tileM=(row>>4)&7 (x256), ks=(col>>3)&1 (x128),
//   lane=(row&7)*4+(col&3) (x4), reg=((row>>3)&1) + ((col>>2)&1)*2
__device__ __forceinline__ size_t afrag_idx(int row, int col, int K) {
  return ((size_t)(row >> 7) * (K >> 4) + (col >> 4)) * 2048 +
         (((row >> 4) & 7) << 8) + (((col >> 3) & 1) << 7) +
         ((((row & 7) << 2) + (col & 3)) << 2) + ((row >> 3) & 1) +
         (((col >> 2) & 1) << 1);
}

// ---------------------------------------------------------------------------
// Weight pack (B-fragment order)
// ---------------------------------------------------------------------------
__global__ void __launch_bounds__(256) wpack_kernel(
    const float* __restrict__ W, float* __restrict__ Wp, int NT8, int K, int total) {
  int idx = blockIdx.x * 256 + threadIdx.x;
  if (idx >= total) return;
  int lane = idx & 31;
  int ks = (idx >> 5) & 1;
  int t2 = idx >> 6;
  int tileN = t2 % NT8;
  int kt = t2 / NT8;
  int n = tileN * 8 + (lane >> 2);
  int k = kt * 16 + ks * 8 + (lane & 3);
  const float* src = W + (size_t)n * K + k;
  float2 v = make_float2(tf32f(src[0]), tf32f(src[4]));
  *(float2*)(Wp + (size_t)idx * 2) = v;
}

// ---------------------------------------------------------------------------
// LayerNorm: output tf32-rounded, A-fragment packed (consumer K=1024)
// ---------------------------------------------------------------------------
__global__ void __launch_bounds__(256) ln_kernel(
    const float* __restrict__ in, const float* __restrict__ w,
    const float* __restrict__ b, float* __restrict__ out, int remap) {
  int row = blockIdx.x;
  int out_row = remap ? ((row & 7) * 1024 + (row >> 3)) : row;
  const float* xr = in + (size_t)row * DMODEL;
  int t = threadIdx.x;
  float v[4];
  float s = 0.f, ss = 0.f;
#pragma unroll
  for (int i = 0; i < 4; i++) {
    v[i] = xr[t + 256 * i];
    s += v[i];
    ss += v[i] * v[i];
  }
#pragma unroll
  for (int o = 16; o > 0; o >>= 1) {
    s += __shfl_xor_sync(0xffffffffu, s, o);
    ss += __shfl_xor_sync(0xffffffffu, ss, o);
  }
  __shared__ float rs[8], rss[8];
  int warp = t >> 5, lane = t & 31;
  if (lane == 0) { rs[warp] = s; rss[warp] = ss; }
  __syncthreads();
  if (t == 0) {
    float a = 0.f, c = 0.f;
#pragma unroll
    for (int i = 0; i < 8; i++) { a += rs[i]; c += rss[i]; }
    rs[0] = a; rss[0] = c;
  }
  __syncthreads();
  float mean = rs[0] * (1.f / 1024.f);
  float var = rss[0] * (1.f / 1024.f) - mean * mean;
  float rstd = rsqrtf(var + 1e-5f);
#pragma unroll
  for (int i = 0; i < 4; i++) {
    int c = t + 256 * i;
    out[afrag_idx(out_row, c, DMODEL)] = tf32f((v[i] - mean) * rstd * w[c] + b[c]);
  }
}

// ---------------------------------------------------------------------------
// tf32 NT GEMM v3: 128x128 block tile, 4 warps (64x64 warp tile), BK=16,
// 3-stage identity cp.async, fragment-packed A (LDS.128) and B (LDS.64).
// One __syncthreads per k-tile.
// ---------------------------------------------------------------------------
template <int EPI, bool REMAP, bool RND, bool AFRAG>
__global__ void __launch_bounds__(128) gemm_tc(
    const float* __restrict__ Ap, const float* __restrict__ Bp,
    const float* __restrict__ bias, const float* __restrict__ res,
    float* __restrict__ C, int N, int K) {
  __shared__ __align__(16) float As[3][2048];
  __shared__ __align__(16) float Bs[3][2048];
  int tid = threadIdx.x;
  int lane = tid & 31, warp = tid >> 5;
  int wm = warp >> 1, wn = warp & 1;
  int KT = K >> 4, NT8 = N >> 3;
  const float* Asrc = Ap + (size_t)blockIdx.y * KT * 2048;

  float acc[4][8][4];
#pragma unroll
  for (int mi = 0; mi < 4; mi++)
#pragma unroll
    for (int ni = 0; ni < 8; ni++)
#pragma unroll
      for (int r = 0; r < 4; r++) acc[mi][ni][r] = 0.f;

  auto load_stage = [&](int kt, int buf) {
    const float* Bsrc = Bp + ((size_t)kt * NT8 + blockIdx.x * 16) * 128;
    const float* Aks = Asrc + (size_t)kt * 2048;
#pragma unroll
    for (int it = 0; it < 4; it++) {
      int task = (tid + it * 128) * 4;
      uint32_t da = (uint32_t)__cvta_generic_to_shared(&As[buf][task]);
      asm volatile("cp.async.cg.shared.global [%0], [%1], 16;" ::"r"(da), "l"(Aks + task));
      uint32_t db = (uint32_t)__cvta_generic_to_shared(&Bs[buf][task]);
      asm volatile("cp.async.cg.shared.global [%0], [%1], 16;" ::"r"(db), "l"(Bsrc + task));
    }
    asm volatile("cp.async.commit_group;");
  };

  load_stage(0, 0);
  if (KT > 1) load_stage(1, 1);

  for (int kt = 0; kt < KT; kt++) {
    int buf = kt % 3;
    if (kt + 1 < KT) {
      asm volatile("cp.async.wait_group 1;");
    } else {
      asm volatile("cp.async.wait_group 0;");
    }
    __syncthreads();

    // A: warp-half wm covers tileM wm*4..wm*4+3 -> float base wm*4*256
    // B: warp-half wn covers tileN wn*8..wn*8+7 -> float base wn*8*128
    const float4* Af = (const float4*)&As[buf][wm * 1024];
    const float2* Bf = (const float2*)&Bs[buf][wn * 1024];
#pragma unroll
    for (int ks = 0; ks < 2; ks++) {
      float4 af[4];
      float2 bf[8];
#pragma unroll
      for (int mi = 0; mi < 4; mi++) af[mi] = Af[(mi * 2 + ks) * 32 + lane];
#pragma unroll
      for (int ni = 0; ni < 8; ni++) bf[ni] = Bf[(ni * 2 + ks) * 32 + lane];
#pragma unroll
      for (int mi = 0; mi < 4; mi++)
#pragma unroll
        for (int ni = 0; ni < 8; ni++) {
          asm volatile(
              "mma.sync.aligned.m16n8k8.row.col.f32.tf32.tf32.f32 "
              "{%0,%1,%2,%3}, {%4,%5,%6,%7}, {%8,%9}, {%0,%1,%2,%3};"
              : "+f"(acc[mi][ni][0]), "+f"(acc[mi][ni][1]),
                "+f"(acc[mi][ni][2]), "+f"(acc[mi][ni][3])
              : "r"(__float_as_uint(af[mi].x)), "r"(__float_as_uint(af[mi].y)),
                "r"(__float_as_uint(af[mi].z)), "r"(__float_as_uint(af[mi].w)),
                "r"(__float_as_uint(bf[ni].x)), "r"(__float_as_uint(bf[ni].y)));
        }
    }
    // issue next stage AFTER compute: its buffer was consumed 2 iters ago,
    // ordered by the barrier at the top of this iteration.
    if (kt + 2 < KT) load_stage(kt + 2, (kt + 2) % 3);
  }

#pragma unroll
  for (int mi = 0; mi < 4; mi++) {
#pragma unroll
    for (int half = 0; half < 2; half++) {
      int r = blockIdx.y * 128 + wm * 64 + mi * 16 + (lane >> 2) + half * 8;
      int om = REMAP ? ((r & 1023) * 8 + (r >> 10)) : r;
      float* crow = C + (size_t)om * N;
      const float* rrow = (EPI == 2) ? res + (size_t)om * N : nullptr;
#pragma unroll
      for (int ni = 0; ni < 8; ni++) {
        int cix = blockIdx.x * 128 + wn * 64 + ni * 8 + (lane & 3) * 2;
        float v0 = acc[mi][ni][half * 2 + 0] + bias[cix];
        float v1 = acc[mi][ni][half * 2 + 1] + bias[cix + 1];
        if (EPI == 1) {
          v0 = v0 * (1.f / (1.f + __expf(-1.702f * v0)));
          v1 = v1 * (1.f / (1.f + __expf(-1.702f * v1)));
        }
        if (EPI == 2) {
          v0 += rrow[cix];
          v1 += rrow[cix + 1];
        }
        if (RND) { v0 = tf32f(v0); v1 = tf32f(v1); }
        if (AFRAG) {
          C[afrag_idx(om, cix, N)] = v0;
          C[afrag_idx(om, cix + 1, N)] = v1;
        } else {
          *(float2*)&crow[cix] = make_float2(v0, v1);
        }
      }
    }
  }
}

// ---------------------------------------------------------------------------
// tf32 MMA flash attention (output A-fragment packed for out-proj GEMM)
// ---------------------------------------------------------------------------
__device__ __forceinline__ void mma8(float* d, const float4& a, float b0, float b1) {
  asm volatile(
      "mma.sync.aligned.m16n8k8.row.col.f32.tf32.tf32.f32 "
      "{%0,%1,%2,%3}, {%4,%5,%6,%7}, {%8,%9}, {%0,%1,%2,%3};"
      : "+f"(d[0]), "+f"(d[1]), "+f"(d[2]), "+f"(d[3])
      : "r"(__float_as_uint(a.x)), "r"(__float_as_uint(a.y)),
        "r"(__float_as_uint(a.z)), "r"(__float_as_uint(a.w)),
        "r"(__float_as_uint(b0)), "r"(__float_as_uint(b1)));
}

__global__ void __launch_bounds__(256) attn_mma(const float* __restrict__ qkv,
                                                float* __restrict__ out) {
  extern __shared__ float sm[];
  float* Qf = sm;
  float* KfA = sm + 8192;
  float* KfB = sm + 12288;
  float* Vf = sm + 16384;
  float* Pf = sm + 20480;

  int tid = threadIdx.x, lane = tid & 31, w = tid >> 5;
  int qt = blockIdx.x, h = blockIdx.y, n = blockIdx.z;
  const float* base = qkv + (size_t)n * 1024 * 3072;
  const float* qb = base + h * 64;
  const float* kb = base + 1024 + h * 64;
  const float* vb = base + 2048 + h * 64;

#pragma unroll
  for (int j = 0; j < 8; j++) {
    int e = tid + j * 256;
    int row = e >> 4, c0 = (e & 15) << 2;
    float4 q = *(const float4*)(qb + (size_t)(qt * 128 + row) * 3072 + c0);
    int wq = row >> 4, rl = row & 15;
    int idx = wq * 1024 + ((c0 >> 3) * 32 + (rl & 7) * 4) * 4 + (rl >> 3) + ((c0 >> 2) & 1) * 2;
    Qf[idx] = q.x * 0.125f;
    Qf[idx + 4] = q.y * 0.125f;
    Qf[idx + 8] = q.z * 0.125f;
    Qf[idx + 12] = q.w * 0.125f;
  }

  float4 ka[4];
#pragma unroll
  for (int j = 0; j < 4; j++) {
    int e = tid + j * 256;
    int key = e >> 4, c0 = (e & 15) << 2;
    ka[j] = *(const float4*)(kb + (size_t)key * 3072 + c0);
  }
#pragma unroll
  for (int j = 0; j < 4; j++) {
    int e = tid + j * 256;
    int key = e >> 4, c0 = (e & 15) << 2;
    int nt = key >> 3, ks = c0 >> 3;
    int idx = ((nt * 4 + (ks >> 1)) * 32 + (key & 7) * 4) * 4 + (ks & 1) * 2 + ((c0 >> 2) & 1);
    KfA[idx] = ka[j].x; KfA[idx + 4] = ka[j].y;
    KfA[idx + 8] = ka[j].z; KfA[idx + 12] = ka[j].w;
  }
  __syncthreads();

  float m0 = -1e30f, m1 = -1e30f, l0 = 0.f, l1 = 0.f;
  float o[8][4];
#pragma unroll
  for (int nt = 0; nt < 8; nt++)
#pragma unroll
    for (int r = 0; r < 4; r++) o[nt][r] = 0.f;

  float* Pw = Pf + w * 1024;
  const float4* Qr = (const float4*)(Qf + w * 1024);
  const float4* Pr = (const float4*)(Pf + w * 1024);
  const float4* Vr = (const float4*)Vf;

  int kl0 = (lane & 3) * 2;
  int dl0 = (lane >> 2) * 4 + (kl0 & 3);
  int dl1 = (lane >> 2) * 4 + ((kl0 + 1) & 3);
  int rb0 = ((kl0 >> 2) & 1) * 2;
  int rb1 = (((kl0 + 1) >> 2) & 1) * 2;

  for (int kt = 0; kt < 16; kt++) {
    float* Kcur = (kt & 1) ? KfB : KfA;
    float* Knxt = (kt & 1) ? KfA : KfB;

    float4 va[4];
#pragma unroll
    for (int j = 0; j < 4; j++) {
      int e = tid + j * 256;
      int key = e >> 4, c0 = (e & 15) << 2;
      va[j] = *(const float4*)(vb + (size_t)(kt * 64 + key) * 3072 + c0);
      if (kt < 15)
        ka[j] = *(const float4*)(kb + (size_t)((kt + 1) * 64 + key) * 3072 + c0);
    }

    float s[8][4];
#pragma unroll
    for (int nt = 0; nt < 8; nt++)
#pragma unroll
      for (int r = 0; r < 4; r++) s[nt][r] = 0.f;
    const float4* Kr = (const float4*)Kcur;
#pragma unroll
    for (int kp = 0; kp < 4; kp++) {
      float4 a0 = Qr[(kp * 2) * 32 + lane];
      float4 a1 = Qr[(kp * 2 + 1) * 32 + lane];
#pragma unroll
      for (int nt = 0; nt < 8; nt++) {
        float4 b = Kr[(nt * 4 + kp) * 32 + lane];
        mma8(s[nt], a0, b.x, b.y);
        mma8(s[nt], a1, b.z, b.w);
      }
    }

    float mx0 = -1e30f, mx1 = -1e30f;
#pragma unroll
    for (int nt = 0; nt < 8; nt++) {
      mx0 = fmaxf(mx0, fmaxf(s[nt][0], s[nt][1]));
      mx1 = fmaxf(mx1, fmaxf(s[nt][2], s[nt][3]));
    }
    mx0 = fmaxf(mx0, __shfl_xor_sync(0xffffffffu, mx0, 1));
    mx0 = fmaxf(mx0, __shfl_xor_sync(0xffffffffu, mx0, 2));
    mx1 = fmaxf(mx1, __shfl_xor_sync(0xffffffffu, mx1, 1));
    mx1 = fmaxf(mx1, __shfl_xor_sync(0xffffffffu, mx1, 2));
    float mn0 = fmaxf(m0, mx0), mn1 = fmaxf(m1, mx1);
    float a0s = __expf(m0 - mn0), a1s = __expf(m1 - mn1);
    float ls0 = 0.f, ls1 = 0.f;
#pragma unroll
    for (int nt = 0; nt < 8; nt++) {
      float p00 = __expf(s[nt][0] - mn0);
      float p01 = __expf(s[nt][1] - mn0);
      float p10 = __expf(s[nt][2] - mn1);
      float p11 = __expf(s[nt][3] - mn1);
      ls0 += p00 + p01;
      ls1 += p10 + p11;
      Pw[(nt * 32 + dl0) * 4 + rb0] = tf32f(p00);
      Pw[(nt * 32 + dl1) * 4 + rb1] = tf32f(p01);
      Pw[(nt * 32 + dl0) * 4 + rb0 + 1] = tf32f(p10);
      Pw[(nt * 32 + dl1) * 4 + rb1 + 1] = tf32f(p11);
    }
    ls0 += __shfl_xor_sync(0xffffffffu, ls0, 1);
    ls0 += __shfl_xor_sync(0xffffffffu, ls0, 2);
    ls1 += __shfl_xor_sync(0xffffffffu, ls1, 1);
    ls1 += __shfl_xor_sync(0xffffffffu, ls1, 2);
    l0 = l0 * a0s + ls0;
    l1 = l1 * a1s + ls1;
    m0 = mn0; m1 = mn1;
#pragma unroll
    for (int nt = 0; nt < 8; nt++) {
      o[nt][0] *= a0s; o[nt][1] *= a0s;
      o[nt][2] *= a1s; o[nt][3] *= a1s;
    }
    __syncwarp();

#pragma unroll
    for (int j = 0; j < 4; j++) {
      int e = tid + j * 256;
      int key = e >> 4, c0 = (e & 15) << 2;
      int nt = c0 >> 3, ks = key >> 3;
      int idx = ((nt * 4 + (ks >> 1)) * 32 + (c0 & 7) * 4 + (key & 3)) * 4 +
                (ks & 1) * 2 + ((key >> 2) & 1);
      Vf[idx] = va[j].x; Vf[idx + 16] = va[j].y;
      Vf[idx + 32] = va[j].z; Vf[idx + 48] = va[j].w;
    }
    __syncthreads();

#pragma unroll
    for (int kp = 0; kp < 4; kp++) {
      float4 a0 = Pr[(kp * 2) * 32 + lane];
      float4 a1 = Pr[(kp * 2 + 1) * 32 + lane];
#pragma unroll
      for (int nt = 0; nt < 8; nt++) {
        float4 b = Vr[(nt * 4 + kp) * 32 + lane];
        mma8(o[nt], a0, b.x, b.y);
        mma8(o[nt], a1, b.z, b.w);
      }
    }

    if (kt < 15) {
#pragma unroll
      for (int j = 0; j < 4; j++) {
        int e = tid + j * 256;
        int key = e >> 4, c0 = (e & 15) << 2;
        int nt = key >> 3, ks = c0 >> 3;
        int idx = ((nt * 4 + (ks >> 1)) * 32 + (key & 7) * 4) * 4 + (ks & 1) * 2 + ((c0 >> 2) & 1);
        Knxt[idx] = ka[j].x; Knxt[idx + 4] = ka[j].y;
        Knxt[idx + 8] = ka[j].z; Knxt[idx + 12] = ka[j].w;
      }
    }
    __syncthreads();
  }

  // ---- output: A-fragment packed for the out-proj GEMM (K=1024) ----
  float rl0 = 1.f / l0, rl1 = 1.f / l1;
  int row0 = n * 1024 + qt * 128 + w * 16 + (lane >> 2);
  int row1 = row0 + 8;
#pragma unroll
  for (int nt = 0; nt < 8; nt++) {
    int c = h * 64 + nt * 8 + (lane & 3) * 2;
    out[afrag_idx(row0, c, DMODEL)]     = tf32f(o[nt][0] * rl0);
    out[afrag_idx(row0, c + 1, DMODEL)] = tf32f(o[nt][1] * rl0);
    out[afrag_idx(row1, c, DMODEL)]     = tf32f(o[nt][2] * rl1);
    out[afrag_idx(row1, c + 1, DMODEL)] = tf32f(o[nt][3] * rl1);
  }
}

// ---------------------------------------------------------------------------
extern "C" void kernel_launch(void* const* d_in, const int* in_sizes, int n_in,
                              void* d_out, int out_size) {
  const float* x      = (const float*)d_in[0];
  const float* ln1_w  = (const float*)d_in[1];
  const float* ln1_b  = (const float*)d_in[2];
  const float* in_w   = (const float*)d_in[3];
  const float* in_b   = (const float*)d_in[4];
  const float* out_w  = (const float*)d_in[5];
  const float* out_b  = (const float*)d_in[6];
  const float* ln2_w  = (const float*)d_in[7];
  const float* ln2_b  = (const float*)d_in[8];
  const float* fc_w   = (const float*)d_in[9];
  const float* fc_b   = (const float*)d_in[10];
  const float* proj_w = (const float*)d_in[11];
  const float* proj_b = (const float*)d_in[12];
  float* out = (float*)d_out;

  float *h, *qkv, *attn, *x1, *h2, *fc, *wq, *wo, *wf, *wp;
  cudaGetSymbolAddress((void**)&h, g_h);
  cudaGetSymbolAddress((void**)&qkv, g_qkv);
  cudaGetSymbolAddress((void**)&attn, g_attn);
  cudaGetSymbolAddress((void**)&x1, g_x1);
  cudaGetSymbolAddress((void**)&h2, g_h2);
  cudaGetSymbolAddress((void**)&fc, g_fc);
  cudaGetSymbolAddress((void**)&wq, g_wq);
  cudaGetSymbolAddress((void**)&wo, g_wo);
  cudaGetSymbolAddress((void**)&wf, g_wf);
  cudaGetSymbolAddress((void**)&wp, g_wp);

  static int smem_set = 0;
  if (!smem_set) {
    cudaFuncSetAttribute(attn_mma, cudaFuncAttributeMaxDynamicSharedMemorySize, 114688);
    smem_set = 1;
  }

  // 0. weight round + B-fragment pack
  wpack_kernel<<<6144, 256>>>(in_w, wq, 384, 1024, 3 * 1024 * 1024 / 2);
  wpack_kernel<<<2048, 256>>>(out_w, wo, 128, 1024, 1024 * 1024 / 2);
  wpack_kernel<<<8192, 256>>>(fc_w, wf, 512, 1024, 4 * 1024 * 1024 / 2);
  wpack_kernel<<<8192, 256>>>(proj_w, wp, 128, 4096, 4 * 1024 * 1024 / 2);

  // 1. LN1 -> h (n-major rows, A-frag packed)
  ln_kernel<<<8192, 256>>>(x, ln1_w, ln1_b, h, 1);
  // 2. qkv = h @ in_w^T + in_b (row-major out; feeds attention)
  gemm_tc<0, false, true, false><<<dim3(24, 64), 128>>>(h, wq, in_b, nullptr, qkv, 3072, 1024);
  // 3. attention -> attn (A-frag packed)
  attn_mma<<<dim3(8, 16, 8), 256, 114688>>>(qkv, attn);
  // 4. x1 = x + attn @ out_w^T + out_b (row-major s-major)
  gemm_tc<2, true, false, false><<<dim3(8, 64), 128>>>(attn, wo, out_b, x, x1, 1024, 1024);
  // 5. LN2 -> h2 (A-frag packed)
  ln_kernel<<<8192, 256>>>(x1, ln2_w, ln2_b, h2, 0);
  // 6. fc = QuickGELU(h2 @ fc_w^T + fc_b) (A-frag packed, consumer K=4096)
  gemm_tc<1, false, true, true><<<dim3(32, 64), 128>>>(h2, wf, fc_b, nullptr, fc, 4096, 1024);
  // 7. out = x1 + fc @ proj_w^T + proj_b (row-major final output)
  gemm_tc<2, false, false, false><<<dim3(8, 64), 128>>>(fc, wp, proj_b, x1, out, 1024, 4096);
}